// round 1
// baseline (speedup 1.0000x reference)
#include <cuda_runtime.h>
#include <math.h>

// Problem dims (fixed by reference)
#define BATCH 8
#define CCH   512
#define NSEQ  1024          // H*W = 32*32
#define NCOLS 8192          // BATCH * NSEQ
#define NH    8
#define HD    64
#define NGRP  32

// Scratch (device globals: allocation-free rule)
__device__ float g_xn [CCH  * NCOLS];   // [C][B*N]  normalized input
__device__ float g_qkv[3*CCH * NCOLS]; // [3C][B*N]
__device__ float g_att[CCH  * NCOLS];   // [C][B*N]  attention output

// ---------------------------------------------------------------------------
// GroupNorm: per (b, g) over 16 channels x 1024. Writes transposed layout
// xn[c][b*1024 + n] so downstream GEMMs are single big GEMMs.
// ---------------------------------------------------------------------------
__global__ void __launch_bounds__(256) gn_kernel(const float* __restrict__ x,
                                                 const float* __restrict__ gw,
                                                 const float* __restrict__ gb) {
    int bg = blockIdx.x;
    int b = bg >> 5, g = bg & 31;
    const float* xp = x + (size_t)b * CCH * NSEQ + (size_t)g * 16 * NSEQ;

    float s = 0.f, s2 = 0.f;
    // 16 channels * 1024 = 16384 floats = 4096 float4
    for (int i = threadIdx.x; i < 4096; i += 256) {
        float4 v = ((const float4*)xp)[i];
        s  += v.x + v.y + v.z + v.w;
        s2 += v.x*v.x + v.y*v.y + v.z*v.z + v.w*v.w;
    }
    // warp reduce
    #pragma unroll
    for (int o = 16; o > 0; o >>= 1) {
        s  += __shfl_xor_sync(0xffffffffu, s,  o);
        s2 += __shfl_xor_sync(0xffffffffu, s2, o);
    }
    __shared__ float rs[8], rs2[8];
    if ((threadIdx.x & 31) == 0) { rs[threadIdx.x >> 5] = s; rs2[threadIdx.x >> 5] = s2; }
    __syncthreads();
    float tot = 0.f, tot2 = 0.f;
    #pragma unroll
    for (int i = 0; i < 8; i++) { tot += rs[i]; tot2 += rs2[i]; }
    const float inv_cnt = 1.f / 16384.f;
    float mean = tot * inv_cnt;
    float var  = tot2 * inv_cnt - mean * mean;
    float rstd = rsqrtf(var + 1e-5f);

    for (int i = threadIdx.x; i < 4096; i += 256) {
        int c = g * 16 + (i >> 8);          // 256 float4 per channel
        float4 v = ((const float4*)xp)[i];
        float wch = gw[c] * rstd;
        float bch = gb[c] - mean * wch;
        float4 o;
        o.x = v.x * wch + bch; o.y = v.y * wch + bch;
        o.z = v.z * wch + bch; o.w = v.w * wch + bch;
        ((float4*)(g_xn + (size_t)c * NCOLS + (size_t)b * NSEQ))[i & 255] = o;
    }
}

// ---------------------------------------------------------------------------
// Tiled fp32 GEMM: C[M x 8192] = A[M x 512] * Bsrc[512 x 8192] (+bias, +resid)
// mode 0: Bsrc = g_xn,  Cdst = g_qkv    (QKV projection)
// mode 1: Bsrc = g_att, Cdst = d_out (layout [b][row][n]) + residual x
// Tile 128x128x16, 256 threads, 8x8 microtile. All dims divide evenly.
// ---------------------------------------------------------------------------
__global__ void __launch_bounds__(256) gemm_kernel(const float* __restrict__ A,
                                                   const float* __restrict__ bias,
                                                   float* __restrict__ outParam,
                                                   const float* __restrict__ resid,
                                                   int mode) {
    const float* Bsrc = (mode == 0) ? g_xn : g_att;
    float* C          = (mode == 0) ? g_qkv : outParam;

    __shared__ float As[16][132];   // [k][m], padded to dodge STS conflicts
    __shared__ float Bs[16][128];   // [k][n]

    const int bm = blockIdx.y, bn = blockIdx.x;
    const int tid = threadIdx.x;
    const int ty = tid >> 4, tx = tid & 15;
    const float* Ap = A + (size_t)bm * 128 * CCH;

    float acc[8][8];
    #pragma unroll
    for (int i = 0; i < 8; i++)
        #pragma unroll
        for (int j = 0; j < 8; j++) acc[i][j] = 0.f;

    for (int k0 = 0; k0 < CCH; k0 += 16) {
        // A tile: 128 rows x 16 k = 512 float4; store transposed
        #pragma unroll
        for (int l = 0; l < 2; l++) {
            int i = tid + l * 256;
            int row = i >> 2, c4 = (i & 3) << 2;
            float4 v = *(const float4*)(Ap + (size_t)row * CCH + k0 + c4);
            As[c4 + 0][row] = v.x; As[c4 + 1][row] = v.y;
            As[c4 + 2][row] = v.z; As[c4 + 3][row] = v.w;
        }
        // B tile: 16 k x 128 n = 512 float4
        #pragma unroll
        for (int l = 0; l < 2; l++) {
            int i = tid + l * 256;
            int k = i >> 5, n4 = (i & 31) << 2;
            *(float4*)&Bs[k][n4] =
                *(const float4*)(Bsrc + (size_t)(k0 + k) * NCOLS + bn * 128 + n4);
        }
        __syncthreads();
        #pragma unroll
        for (int kk = 0; kk < 16; kk++) {
            float a[8], bb[8];
            #pragma unroll
            for (int i = 0; i < 8; i++) a[i]  = As[kk][ty * 8 + i];
            #pragma unroll
            for (int j = 0; j < 8; j++) bb[j] = Bs[kk][tx * 8 + j];
            #pragma unroll
            for (int i = 0; i < 8; i++)
                #pragma unroll
                for (int j = 0; j < 8; j++) acc[i][j] += a[i] * bb[j];
        }
        __syncthreads();
    }

    const int colBase = bn * 128 + tx * 8;
    #pragma unroll
    for (int i = 0; i < 8; i++) {
        const int row = bm * 128 + ty * 8 + i;
        const float bv = bias[row];
        if (mode == 1) {
            #pragma unroll
            for (int j4 = 0; j4 < 2; j4++) {
                int col = colBase + j4 * 4;
                int bb_ = col >> 10, n = col & 1023;
                size_t idx = (size_t)bb_ * CCH * NSEQ + (size_t)row * NSEQ + n;
                float4 rv = *(const float4*)(resid + idx);
                float4 o;
                o.x = acc[i][j4*4+0] + bv + rv.x;
                o.y = acc[i][j4*4+1] + bv + rv.y;
                o.z = acc[i][j4*4+2] + bv + rv.z;
                o.w = acc[i][j4*4+3] + bv + rv.w;
                *(float4*)(C + idx) = o;
            }
        } else {
            #pragma unroll
            for (int j4 = 0; j4 < 2; j4++) {
                float4 o;
                o.x = acc[i][j4*4+0] + bv;
                o.y = acc[i][j4*4+1] + bv;
                o.z = acc[i][j4*4+2] + bv;
                o.w = acc[i][j4*4+3] + bv;
                *(float4*)(C + (size_t)row * NCOLS + colBase + j4 * 4) = o;
            }
        }
    }
}

// ---------------------------------------------------------------------------
// Attention: per (b, h), softmax(q k^T / 8) v, flash-style online softmax.
// Block = 128 threads = 128 queries. K/V tiles 64(d) x 64(m) in smem.
// q/k/v rows live in g_qkv at row (s*512 + h*64 + d), col (b*1024 + n).
// ---------------------------------------------------------------------------
__global__ void __launch_bounds__(128) attn_kernel() {
    const int b = blockIdx.z, h = blockIdx.y, qt = blockIdx.x;
    const int t = threadIdx.x;
    const int n0 = qt * 128;

    const float* Qb = g_qkv + (size_t)(h * HD)            * NCOLS + b * NSEQ;
    const float* Kb = g_qkv + (size_t)(CCH   + h * HD)    * NCOLS + b * NSEQ;
    const float* Vb = g_qkv + (size_t)(2*CCH + h * HD)    * NCOLS + b * NSEQ;
    const float scale = 0.125f;   // 64^-0.5

    float q[HD], acc[HD];
    #pragma unroll
    for (int d = 0; d < HD; d++) {
        q[d] = Qb[(size_t)d * NCOLS + n0 + t] * scale;
        acc[d] = 0.f;
    }
    float mmax = -1e30f, l = 0.f;

    __shared__ float ks[HD][64];
    __shared__ float vs[HD][64];

    for (int kt = 0; kt < NSEQ / 64; kt++) {
        const int m0 = kt * 64;
        __syncthreads();
        #pragma unroll
        for (int f = t; f < 1024; f += 128) {   // 64x64 = 1024 float4 each
            int d = f >> 4, m4 = (f & 15) << 2;
            *(float4*)&ks[d][m4] = *(const float4*)(Kb + (size_t)d * NCOLS + m0 + m4);
            *(float4*)&vs[d][m4] = *(const float4*)(Vb + (size_t)d * NCOLS + m0 + m4);
        }
        __syncthreads();

        #pragma unroll 1
        for (int c0 = 0; c0 < 64; c0 += 16) {
            float s[16];
            #pragma unroll
            for (int j = 0; j < 16; j++) s[j] = 0.f;
            #pragma unroll
            for (int d = 0; d < HD; d++) {
                float qd = q[d];
                #pragma unroll
                for (int j = 0; j < 16; j++) s[j] += qd * ks[d][c0 + j];
            }
            float cmax = mmax;
            #pragma unroll
            for (int j = 0; j < 16; j++) cmax = fmaxf(cmax, s[j]);
            float fs = __expf(mmax - cmax);
            mmax = cmax;
            l *= fs;
            #pragma unroll
            for (int d = 0; d < HD; d++) acc[d] *= fs;
            float psum = 0.f;
            #pragma unroll
            for (int j = 0; j < 16; j++) {
                float p = __expf(s[j] - cmax);
                psum += p;
                s[j] = p;
            }
            l += psum;
            #pragma unroll
            for (int j = 0; j < 16; j++) {
                float p = s[j];
                #pragma unroll
                for (int d = 0; d < HD; d++) acc[d] += p * vs[d][c0 + j];
            }
        }
    }

    const float inv = 1.f / l;
    float* Ob = g_att + (size_t)(h * HD) * NCOLS + b * NSEQ + n0 + t;
    #pragma unroll
    for (int d = 0; d < HD; d++) Ob[(size_t)d * NCOLS] = acc[d] * inv;
}

// ---------------------------------------------------------------------------
// Launch
// ---------------------------------------------------------------------------
extern "C" void kernel_launch(void* const* d_in, const int* in_sizes, int n_in,
                              void* d_out, int out_size) {
    const float* x      = (const float*)d_in[0];
    const float* gn_w   = (const float*)d_in[1];
    const float* gn_b   = (const float*)d_in[2];
    const float* qkv_w  = (const float*)d_in[3];
    const float* qkv_b  = (const float*)d_in[4];
    const float* proj_w = (const float*)d_in[5];
    const float* proj_b = (const float*)d_in[6];
    float* out = (float*)d_out;

    gn_kernel<<<BATCH * NGRP, 256>>>(x, gn_w, gn_b);

    // QKV: M = 1536 -> 12 row tiles, 64 col tiles
    gemm_kernel<<<dim3(NCOLS / 128, (3 * CCH) / 128), 256>>>(
        qkv_w, qkv_b, nullptr, nullptr, 0);

    attn_kernel<<<dim3(NSEQ / 128, NH, BATCH), 128>>>();

    // Proj: M = 512 -> 4 row tiles; writes d_out with residual
    gemm_kernel<<<dim3(NCOLS / 128, CCH / 128), 256>>>(
        proj_w, proj_b, out, x, 1);
}

// round 4
// speedup vs baseline: 1.5366x; 1.5366x over previous
#include <cuda_runtime.h>
#include <math.h>
#include <stdint.h>

#define BATCH 8
#define CCH   512
#define NSEQ  1024
#define NCOLS 8192
#define NH    8
#define HD    64
#define NGRP  32

__device__ float g_xn [CCH  * NCOLS];   // [C][B*N]
__device__ float g_qkv[3*CCH * NCOLS];  // [3C][B*N]
__device__ float g_att[CCH  * NCOLS];   // [C][B*N]

// ---------------- helpers ----------------
__device__ __forceinline__ uint32_t f2tf(float f) {
    uint32_t r;
    asm("cvt.rna.tf32.f32 %0, %1;" : "=r"(r) : "f"(f));
    return r;
}
__device__ __forceinline__ void mma8(float c[4], const uint32_t a[4], const uint32_t b[2]) {
    asm volatile(
        "mma.sync.aligned.m16n8k8.row.col.f32.tf32.tf32.f32 "
        "{%0,%1,%2,%3}, {%4,%5,%6,%7}, {%8,%9}, {%0,%1,%2,%3};"
        : "+f"(c[0]), "+f"(c[1]), "+f"(c[2]), "+f"(c[3])
        : "r"(a[0]), "r"(a[1]), "r"(a[2]), "r"(a[3]), "r"(b[0]), "r"(b[1]));
}

// ---------------------------------------------------------------------------
// GroupNorm: writes xn transposed [C][B*N]
// ---------------------------------------------------------------------------
__global__ void __launch_bounds__(256) gn_kernel(const float* __restrict__ x,
                                                 const float* __restrict__ gw,
                                                 const float* __restrict__ gb) {
    int bg = blockIdx.x;
    int b = bg >> 5, g = bg & 31;
    const float* xp = x + (size_t)b * CCH * NSEQ + (size_t)g * 16 * NSEQ;

    float s = 0.f, s2 = 0.f;
    for (int i = threadIdx.x; i < 4096; i += 256) {
        float4 v = ((const float4*)xp)[i];
        s  += v.x + v.y + v.z + v.w;
        s2 += v.x*v.x + v.y*v.y + v.z*v.z + v.w*v.w;
    }
    #pragma unroll
    for (int o = 16; o > 0; o >>= 1) {
        s  += __shfl_xor_sync(0xffffffffu, s,  o);
        s2 += __shfl_xor_sync(0xffffffffu, s2, o);
    }
    __shared__ float rs[8], rs2[8];
    if ((threadIdx.x & 31) == 0) { rs[threadIdx.x >> 5] = s; rs2[threadIdx.x >> 5] = s2; }
    __syncthreads();
    float tot = 0.f, tot2 = 0.f;
    #pragma unroll
    for (int i = 0; i < 8; i++) { tot += rs[i]; tot2 += rs2[i]; }
    const float inv_cnt = 1.f / 16384.f;
    float mean = tot * inv_cnt;
    float var  = tot2 * inv_cnt - mean * mean;
    float rstd = rsqrtf(var + 1e-5f);

    for (int i = threadIdx.x; i < 4096; i += 256) {
        int c = g * 16 + (i >> 8);
        float4 v = ((const float4*)xp)[i];
        float wch = gw[c] * rstd;
        float bch = gb[c] - mean * wch;
        float4 o;
        o.x = v.x * wch + bch; o.y = v.y * wch + bch;
        o.z = v.z * wch + bch; o.w = v.w * wch + bch;
        ((float4*)(g_xn + (size_t)c * NCOLS + (size_t)b * NSEQ))[i & 255] = o;
    }
}

// ---------------------------------------------------------------------------
// tf32x3 GEMM: C[M x 8192] = A[M x 512] * Bsrc[512 x 8192] (+bias, +resid)
// mode 0: Bsrc=g_xn, C=g_qkv.  mode 1: Bsrc=g_att, C=out [b][row][n] + resid.
// Tile 128x128, k-chunk 16, 256 thr = 8 warps (2M x 4N), warp = 64x32.
// ---------------------------------------------------------------------------
__global__ void __launch_bounds__(256) gemm_kernel(const float* __restrict__ A,
                                                   const float* __restrict__ bias,
                                                   float* __restrict__ outP,
                                                   const float* __restrict__ resid,
                                                   int mode) {
    const float* Bsrc = (mode == 0) ? g_xn : g_att;
    float* C          = (mode == 0) ? g_qkv : outP;

    __shared__ uint32_t Ah[16][136], Al[16][136], Bh[16][136], Bl[16][136];

    const int bm = blockIdx.y, bn = blockIdx.x;
    const int tid = threadIdx.x;
    const int w = tid >> 5, lane = tid & 31;
    const int g = lane >> 2, t4 = lane & 3;
    const int wm = (w >> 2) * 64;
    const int wn = (w & 3) * 32;

    float acc[4][4][4];
    #pragma unroll
    for (int i = 0; i < 4; i++)
        #pragma unroll
        for (int j = 0; j < 4; j++)
            #pragma unroll
            for (int r = 0; r < 4; r++) acc[i][j][r] = 0.f;

    for (int k0 = 0; k0 < CCH; k0 += 16) {
        #pragma unroll
        for (int l = 0; l < 2; l++) {
            int i = tid + l * 256;
            int row = i >> 2, c4 = (i & 3) << 2;
            float4 v = *(const float4*)(A + (size_t)(bm * 128 + row) * CCH + k0 + c4);
            float vv[4];
            vv[0] = v.x; vv[1] = v.y; vv[2] = v.z; vv[3] = v.w;
            #pragma unroll
            for (int e = 0; e < 4; e++) {
                uint32_t hi = f2tf(vv[e]);
                Ah[c4 + e][row] = hi;
                Al[c4 + e][row] = f2tf(vv[e] - __uint_as_float(hi));
            }
        }
        #pragma unroll
        for (int l = 0; l < 2; l++) {
            int i = tid + l * 256;
            int k = i >> 5, n4 = (i & 31) << 2;
            float4 v = *(const float4*)(Bsrc + (size_t)(k0 + k) * NCOLS + bn * 128 + n4);
            uint4 h4, l4;
            h4.x = f2tf(v.x); l4.x = f2tf(v.x - __uint_as_float(h4.x));
            h4.y = f2tf(v.y); l4.y = f2tf(v.y - __uint_as_float(h4.y));
            h4.z = f2tf(v.z); l4.z = f2tf(v.z - __uint_as_float(h4.z));
            h4.w = f2tf(v.w); l4.w = f2tf(v.w - __uint_as_float(h4.w));
            *(uint4*)&Bh[k][n4] = h4;
            *(uint4*)&Bl[k][n4] = l4;
        }
        __syncthreads();

        #pragma unroll
        for (int kk = 0; kk < 16; kk += 8) {
            uint32_t ah[4][4], al[4][4], bh[4][2], bl[4][2];
            #pragma unroll
            for (int i = 0; i < 4; i++) {
                int m0 = wm + i * 16;
                ah[i][0] = Ah[kk + t4][m0 + g];     al[i][0] = Al[kk + t4][m0 + g];
                ah[i][1] = Ah[kk + t4][m0 + g + 8]; al[i][1] = Al[kk + t4][m0 + g + 8];
                ah[i][2] = Ah[kk + t4 + 4][m0 + g];     al[i][2] = Al[kk + t4 + 4][m0 + g];
                ah[i][3] = Ah[kk + t4 + 4][m0 + g + 8]; al[i][3] = Al[kk + t4 + 4][m0 + g + 8];
            }
            #pragma unroll
            for (int j = 0; j < 4; j++) {
                int n0 = wn + j * 8;
                bh[j][0] = Bh[kk + t4][n0 + g];     bl[j][0] = Bl[kk + t4][n0 + g];
                bh[j][1] = Bh[kk + t4 + 4][n0 + g]; bl[j][1] = Bl[kk + t4 + 4][n0 + g];
            }
            #pragma unroll
            for (int i = 0; i < 4; i++)
                #pragma unroll
                for (int j = 0; j < 4; j++) {
                    mma8(acc[i][j], al[i], bh[j]);
                    mma8(acc[i][j], ah[i], bl[j]);
                    mma8(acc[i][j], ah[i], bh[j]);
                }
        }
        __syncthreads();
    }

    #pragma unroll
    for (int i = 0; i < 4; i++) {
        int row0 = bm * 128 + wm + i * 16 + g;
        int row1 = row0 + 8;
        float bv0 = bias[row0], bv1 = bias[row1];
        #pragma unroll
        for (int j = 0; j < 4; j++) {
            int col = bn * 128 + wn + j * 8 + 2 * t4;
            if (mode == 0) {
                float2 o0, o1;
                o0.x = acc[i][j][0] + bv0; o0.y = acc[i][j][1] + bv0;
                o1.x = acc[i][j][2] + bv1; o1.y = acc[i][j][3] + bv1;
                *(float2*)(C + (size_t)row0 * NCOLS + col) = o0;
                *(float2*)(C + (size_t)row1 * NCOLS + col) = o1;
            } else {
                int bb = col >> 10, n = col & 1023;
                size_t i0 = (size_t)bb * CCH * NSEQ + (size_t)row0 * NSEQ + n;
                size_t i1 = (size_t)bb * CCH * NSEQ + (size_t)row1 * NSEQ + n;
                float2 r0 = *(const float2*)(resid + i0);
                float2 r1 = *(const float2*)(resid + i1);
                float2 o0, o1;
                o0.x = acc[i][j][0] + bv0 + r0.x; o0.y = acc[i][j][1] + bv0 + r0.y;
                o1.x = acc[i][j][2] + bv1 + r1.x; o1.y = acc[i][j][3] + bv1 + r1.y;
                *(float2*)(C + i0) = o0;
                *(float2*)(C + i1) = o1;
            }
        }
    }
}

// ---------------------------------------------------------------------------
// Flash attention, tf32 mma. Block = 256 thr (8 warps) = (b, h, 128 q).
// Warp owns 16 q rows. Q frags persistent in regs (scale folded).
// P re-fragmentation via in-warp shuffles (no smem scratch).
// Static smem 37.9 KB (no cudaFuncSetAttribute needed).
// ---------------------------------------------------------------------------
__global__ void __launch_bounds__(256) attn_kernel() {
    const int b = blockIdx.z, h = blockIdx.y, qt = blockIdx.x;
    const int tid = threadIdx.x;
    const int w = tid >> 5, lane = tid & 31;
    const int g = lane >> 2, t4 = lane & 3;

    __shared__ uint32_t Ks[64][72];
    __shared__ uint32_t Vs[64][76];

    const float* Qb = g_qkv + (size_t)(h * HD)             * NCOLS + b * NSEQ;
    const float* Kb = g_qkv + (size_t)(CCH + h * HD)       * NCOLS + b * NSEQ;
    const float* Vb = g_qkv + (size_t)(2 * CCH + h * HD)   * NCOLS + b * NSEQ;

    // Q fragments (A of S-mma), scale folded
    uint32_t qa[8][4];
    {
        const int qq = qt * 128 + w * 16 + g;
        #pragma unroll
        for (int kf = 0; kf < 8; kf++) {
            int d0 = kf * 8 + t4;
            qa[kf][0] = f2tf(Qb[(size_t)d0 * NCOLS + qq] * 0.125f);
            qa[kf][1] = f2tf(Qb[(size_t)d0 * NCOLS + qq + 8] * 0.125f);
            qa[kf][2] = f2tf(Qb[(size_t)(d0 + 4) * NCOLS + qq] * 0.125f);
            qa[kf][3] = f2tf(Qb[(size_t)(d0 + 4) * NCOLS + qq + 8] * 0.125f);
        }
    }

    float Ov[8][4];
    #pragma unroll
    for (int jd = 0; jd < 8; jd++)
        #pragma unroll
        for (int r = 0; r < 4; r++) Ov[jd][r] = 0.f;
    float m0 = -1e30f, m1 = -1e30f, l0 = 0.f, l1 = 0.f;

    for (int kt = 0; kt < NSEQ / 64; kt++) {
        const int mbase = kt * 64;
        __syncthreads();
        for (int f = tid; f < 1024; f += 256) {
            int d = f >> 4, m4 = (f & 15) << 2;
            float4 kv = *(const float4*)(Kb + (size_t)d * NCOLS + mbase + m4);
            float4 vv = *(const float4*)(Vb + (size_t)d * NCOLS + mbase + m4);
            uint4 k4, v4;
            k4.x = f2tf(kv.x); k4.y = f2tf(kv.y); k4.z = f2tf(kv.z); k4.w = f2tf(kv.w);
            v4.x = f2tf(vv.x); v4.y = f2tf(vv.y); v4.z = f2tf(vv.z); v4.w = f2tf(vv.w);
            *(uint4*)&Ks[d][m4] = k4;
            *(uint4*)&Vs[d][m4] = v4;
        }
        __syncthreads();

        // S = Q K^T  (16q x 64m per warp)
        float Csc[8][4];
        #pragma unroll
        for (int j = 0; j < 8; j++)
            #pragma unroll
            for (int r = 0; r < 4; r++) Csc[j][r] = 0.f;
        #pragma unroll
        for (int j = 0; j < 8; j++) {
            #pragma unroll
            for (int kf = 0; kf < 8; kf++) {
                uint32_t bb[2];
                bb[0] = Ks[kf * 8 + t4][j * 8 + g];
                bb[1] = Ks[kf * 8 + t4 + 4][j * 8 + g];
                mma8(Csc[j], qa[kf], bb);
            }
        }

        // online softmax
        float mx0 = m0, mx1 = m1;
        #pragma unroll
        for (int j = 0; j < 8; j++) {
            mx0 = fmaxf(mx0, fmaxf(Csc[j][0], Csc[j][1]));
            mx1 = fmaxf(mx1, fmaxf(Csc[j][2], Csc[j][3]));
        }
        mx0 = fmaxf(mx0, __shfl_xor_sync(0xffffffffu, mx0, 1));
        mx0 = fmaxf(mx0, __shfl_xor_sync(0xffffffffu, mx0, 2));
        mx1 = fmaxf(mx1, __shfl_xor_sync(0xffffffffu, mx1, 1));
        mx1 = fmaxf(mx1, __shfl_xor_sync(0xffffffffu, mx1, 2));
        float f0 = __expf(m0 - mx0), f1 = __expf(m1 - mx1);
        m0 = mx0; m1 = mx1;
        l0 *= f0; l1 *= f1;
        #pragma unroll
        for (int jd = 0; jd < 8; jd++) {
            Ov[jd][0] *= f0; Ov[jd][1] *= f0;
            Ov[jd][2] *= f1; Ov[jd][3] *= f1;
        }

        float s0 = 0.f, s1 = 0.f;
        #pragma unroll
        for (int j = 0; j < 8; j++) {
            Csc[j][0] = __expf(Csc[j][0] - mx0);
            Csc[j][1] = __expf(Csc[j][1] - mx0);
            Csc[j][2] = __expf(Csc[j][2] - mx1);
            Csc[j][3] = __expf(Csc[j][3] - mx1);
            s0 += Csc[j][0] + Csc[j][1];
            s1 += Csc[j][2] + Csc[j][3];
        }
        s0 += __shfl_xor_sync(0xffffffffu, s0, 1);
        s0 += __shfl_xor_sync(0xffffffffu, s0, 2);
        s1 += __shfl_xor_sync(0xffffffffu, s1, 1);
        s1 += __shfl_xor_sync(0xffffffffu, s1, 2);
        l0 += s0; l1 += s1;

        // re-fragment P via shuffles: C-frag (g, 2*t4+p) -> A-frag (g, t4)
        uint32_t pa[8][4];
        const int srcA = (lane & ~3) | (t4 >> 1);
        const int srcB = srcA + 2;
        const bool odd = (t4 & 1);
        #pragma unroll
        for (int mk = 0; mk < 8; mk++) {
            float u0 = __shfl_sync(0xffffffffu, Csc[mk][0], srcA);
            float u1 = __shfl_sync(0xffffffffu, Csc[mk][1], srcA);
            float u2 = __shfl_sync(0xffffffffu, Csc[mk][2], srcA);
            float u3 = __shfl_sync(0xffffffffu, Csc[mk][3], srcA);
            float w0 = __shfl_sync(0xffffffffu, Csc[mk][0], srcB);
            float w1 = __shfl_sync(0xffffffffu, Csc[mk][1], srcB);
            float w2 = __shfl_sync(0xffffffffu, Csc[mk][2], srcB);
            float w3 = __shfl_sync(0xffffffffu, Csc[mk][3], srcB);
            pa[mk][0] = f2tf(odd ? u1 : u0);
            pa[mk][1] = f2tf(odd ? u3 : u2);
            pa[mk][2] = f2tf(odd ? w1 : w0);
            pa[mk][3] = f2tf(odd ? w3 : w2);
        }

        // O += P V   (B[k=m][n=d] = V[d][m])
        #pragma unroll
        for (int jd = 0; jd < 8; jd++) {
            #pragma unroll
            for (int mk = 0; mk < 8; mk++) {
                uint32_t bb[2];
                bb[0] = Vs[jd * 8 + g][mk * 8 + t4];
                bb[1] = Vs[jd * 8 + g][mk * 8 + t4 + 4];
                mma8(Ov[jd], pa[mk], bb);
            }
        }
    }

    // write O / l to g_att [C][B*N]
    float inv0 = 1.f / l0, inv1 = 1.f / l1;
    float* Ob = g_att + (size_t)(h * HD) * NCOLS + b * NSEQ;
    const int q0 = qt * 128 + w * 16 + g;
    #pragma unroll
    for (int jd = 0; jd < 8; jd++) {
        int d0 = jd * 8 + 2 * t4;
        Ob[(size_t)d0 * NCOLS + q0]           = Ov[jd][0] * inv0;
        Ob[(size_t)(d0 + 1) * NCOLS + q0]     = Ov[jd][1] * inv0;
        Ob[(size_t)d0 * NCOLS + q0 + 8]       = Ov[jd][2] * inv1;
        Ob[(size_t)(d0 + 1) * NCOLS + q0 + 8] = Ov[jd][3] * inv1;
    }
}

// ---------------------------------------------------------------------------
extern "C" void kernel_launch(void* const* d_in, const int* in_sizes, int n_in,
                              void* d_out, int out_size) {
    const float* x      = (const float*)d_in[0];
    const float* gn_w   = (const float*)d_in[1];
    const float* gn_b   = (const float*)d_in[2];
    const float* qkv_w  = (const float*)d_in[3];
    const float* qkv_b  = (const float*)d_in[4];
    const float* proj_w = (const float*)d_in[5];
    const float* proj_b = (const float*)d_in[6];
    float* out = (float*)d_out;

    gn_kernel<<<BATCH * NGRP, 256>>>(x, gn_w, gn_b);

    gemm_kernel<<<dim3(NCOLS / 128, (3 * CCH) / 128), 256>>>(
        qkv_w, qkv_b, nullptr, nullptr, 0);

    attn_kernel<<<dim3(NSEQ / 128, NH, BATCH), 256>>>();

    gemm_kernel<<<dim3(NCOLS / 128, CCH / 128), 256>>>(
        proj_w, proj_b, out, x, 1);
}

// round 5
// speedup vs baseline: 2.8197x; 1.8351x over previous
#include <cuda_runtime.h>
#include <cuda_fp16.h>
#include <math.h>
#include <stdint.h>

#define BATCH 8
#define CCH   512
#define NSEQ  1024
#define NCOLS 8192
#define NH    8
#define HD    64
#define NGRP  32
#define QW_ELEMS (3 * CCH * CCH)   // 786432
#define PW_ELEMS (CCH * CCH)       // 262144

// hi/lo half splits (hi+lo ~= fp32 precision)
__device__ __half g_xh[CCH * NCOLS], g_xl[CCH * NCOLS];      // xn
__device__ __half g_wh[QW_ELEMS],    g_wl[QW_ELEMS];         // qkv_w
__device__ __half g_ph[PW_ELEMS],    g_pl[PW_ELEMS];         // proj_w
__device__ __half g_q [3 * CCH * NCOLS];                     // qkv (single half)
__device__ __half g_oh[CCH * NCOLS], g_ol[CCH * NCOLS];      // attention out

// ---------------- helpers ----------------
__device__ __forceinline__ void hsplit(float v, __half& h, __half& l) {
    h = __float2half_rn(v);
    l = __float2half_rn(v - __half2float(h));
}
__device__ __forceinline__ uint32_t pack2(__half lo, __half hi) {
    __half2 p = __halves2half2(lo, hi);
    return *reinterpret_cast<uint32_t*>(&p);
}
__device__ __forceinline__ uint32_t packf2(float lo, float hi) {
    __half2 p = __floats2half2_rn(lo, hi);
    return *reinterpret_cast<uint32_t*>(&p);
}
__device__ __forceinline__ void hmma(float c[4], const uint32_t a[4], const uint32_t b[2]) {
    asm volatile(
        "mma.sync.aligned.m16n8k16.row.col.f32.f16.f16.f32 "
        "{%0,%1,%2,%3}, {%4,%5,%6,%7}, {%8,%9}, {%0,%1,%2,%3};"
        : "+f"(c[0]), "+f"(c[1]), "+f"(c[2]), "+f"(c[3])
        : "r"(a[0]), "r"(a[1]), "r"(a[2]), "r"(a[3]), "r"(b[0]), "r"(b[1]));
}
__device__ __forceinline__ uint32_t prmt(uint32_t a, uint32_t b, uint32_t sel) {
    uint32_t d;
    asm("prmt.b32 %0, %1, %2, %3;" : "=r"(d) : "r"(a), "r"(b), "r"(sel));
    return d;
}

// ---------------------------------------------------------------------------
// GroupNorm: writes xn as hi/lo half, layout [C][B*N]
// ---------------------------------------------------------------------------
__global__ void __launch_bounds__(256) gn_kernel(const float* __restrict__ x,
                                                 const float* __restrict__ gw,
                                                 const float* __restrict__ gb) {
    int bg = blockIdx.x;
    int b = bg >> 5, g = bg & 31;
    const float* xp = x + (size_t)b * CCH * NSEQ + (size_t)g * 16 * NSEQ;

    float s = 0.f, s2 = 0.f;
    for (int i = threadIdx.x; i < 4096; i += 256) {
        float4 v = ((const float4*)xp)[i];
        s  += v.x + v.y + v.z + v.w;
        s2 += v.x*v.x + v.y*v.y + v.z*v.z + v.w*v.w;
    }
    #pragma unroll
    for (int o = 16; o > 0; o >>= 1) {
        s  += __shfl_xor_sync(0xffffffffu, s,  o);
        s2 += __shfl_xor_sync(0xffffffffu, s2, o);
    }
    __shared__ float rs[8], rs2[8];
    if ((threadIdx.x & 31) == 0) { rs[threadIdx.x >> 5] = s; rs2[threadIdx.x >> 5] = s2; }
    __syncthreads();
    float tot = 0.f, tot2 = 0.f;
    #pragma unroll
    for (int i = 0; i < 8; i++) { tot += rs[i]; tot2 += rs2[i]; }
    const float inv_cnt = 1.f / 16384.f;
    float mean = tot * inv_cnt;
    float var  = tot2 * inv_cnt - mean * mean;
    float rstd = rsqrtf(var + 1e-5f);

    for (int i = threadIdx.x; i < 4096; i += 256) {
        int c = g * 16 + (i >> 8);
        float4 v = ((const float4*)xp)[i];
        float wch = gw[c] * rstd;
        float bch = gb[c] - mean * wch;
        float o0 = v.x * wch + bch, o1 = v.y * wch + bch;
        float o2 = v.z * wch + bch, o3 = v.w * wch + bch;
        __half h0, h1, h2, h3, l0, l1, l2, l3;
        hsplit(o0, h0, l0); hsplit(o1, h1, l1);
        hsplit(o2, h2, l2); hsplit(o3, h3, l3);
        size_t base = (size_t)c * NCOLS + (size_t)b * NSEQ;
        uint32_t* oh = (uint32_t*)(g_xh + base);
        uint32_t* ol = (uint32_t*)(g_xl + base);
        int j = (i & 255) * 2;
        oh[j] = pack2(h0, h1); oh[j + 1] = pack2(h2, h3);
        ol[j] = pack2(l0, l1); ol[j + 1] = pack2(l2, l3);
    }
}

// ---------------------------------------------------------------------------
// Weight split prep: qkv_w and proj_w -> hi/lo half
// ---------------------------------------------------------------------------
__global__ void __launch_bounds__(256) prep_w_kernel(const float* __restrict__ qw,
                                                     const float* __restrict__ pw) {
    for (int i = blockIdx.x * 256 + threadIdx.x; i < QW_ELEMS + PW_ELEMS;
         i += gridDim.x * 256) {
        if (i < QW_ELEMS) {
            __half h, l; hsplit(qw[i], h, l);
            g_wh[i] = h; g_wl[i] = l;
        } else {
            __half h, l; hsplit(pw[i - QW_ELEMS], h, l);
            g_ph[i - QW_ELEMS] = h; g_pl[i - QW_ELEMS] = l;
        }
    }
}

// ---------------------------------------------------------------------------
// fp16x3 GEMM: C[M x 8192] = A[M x 512] * B[512 x 8192]  (+bias, +resid)
// A, B pre-split hi/lo half. Smem stores k-pairs packed in u32:
//   Asm[kp][m] = (A[m][2kp], A[m][2kp+1]) ; Bsm[kp][n] = (B[2kp][n], B[2kp+1][n])
// mode 0: B = g_xh/g_xl, C = g_q (half).  mode 1: B = g_oh/g_ol, C = out + resid.
// Tile 128x128, k-chunk 32 (2 k16 steps), 256 thr = 8 warps (2Mx4N), warp 64x32.
// Register prefetch of next chunk overlaps global latency with MMA.
// ---------------------------------------------------------------------------
__global__ void __launch_bounds__(256) gemm_kernel(const float* __restrict__ bias,
                                                   float* __restrict__ outP,
                                                   const float* __restrict__ resid,
                                                   int mode) {
    const __half* Ah_g = mode ? g_ph : g_wh;
    const __half* Al_g = mode ? g_pl : g_wl;
    const __half* Bh_g = mode ? g_oh : g_xh;
    const __half* Bl_g = mode ? g_ol : g_xl;

    __shared__ uint32_t Ash[16][136], Asl[16][136], Bsh[16][136], Bsl[16][136];

    const int bm = blockIdx.y, bn = blockIdx.x;
    const int tid = threadIdx.x;
    const int w = tid >> 5, lane = tid & 31;
    const int g = lane >> 2, t4 = lane & 3;
    const int wm = (w >> 2) * 64;
    const int wn = (w & 3) * 32;

    // load mappings
    const int arow = tid & 127, ahalf = tid >> 7;     // A: 8 u32 from row arow
    const int np = tid & 63, kq = tid >> 6;           // B: pairs

    const uint4* AgH = (const uint4*)(Ah_g + (size_t)(bm * 128 + arow) * CCH);
    const uint4* AgL = (const uint4*)(Al_g + (size_t)(bm * 128 + arow) * CCH);

    float acc[4][4][4];
    #pragma unroll
    for (int i = 0; i < 4; i++)
        #pragma unroll
        for (int j = 0; j < 4; j++)
            #pragma unroll
            for (int r = 0; r < 4; r++) acc[i][j][r] = 0.f;

    uint4 pAh[2], pAl[2];
    uint32_t pBh[4][2], pBl[4][2];

    // prefetch chunk 0
    {
        int u4 = ahalf * 2;   // k0 = 0
        pAh[0] = AgH[u4]; pAh[1] = AgH[u4 + 1];
        pAl[0] = AgL[u4]; pAl[1] = AgL[u4 + 1];
        #pragma unroll
        for (int p = 0; p < 4; p++) {
            int kr = 2 * (p * 4 + kq);
            const uint32_t* r0h = (const uint32_t*)(Bh_g + (size_t)kr * NCOLS) + bn * 64;
            const uint32_t* r1h = (const uint32_t*)(Bh_g + (size_t)(kr + 1) * NCOLS) + bn * 64;
            const uint32_t* r0l = (const uint32_t*)(Bl_g + (size_t)kr * NCOLS) + bn * 64;
            const uint32_t* r1l = (const uint32_t*)(Bl_g + (size_t)(kr + 1) * NCOLS) + bn * 64;
            pBh[p][0] = r0h[np]; pBh[p][1] = r1h[np];
            pBl[p][0] = r0l[np]; pBl[p][1] = r1l[np];
        }
    }

    for (int c = 0; c < 16; c++) {
        __syncthreads();
        // store prefetched chunk
        {
            const uint32_t* a32h = (const uint32_t*)pAh;
            const uint32_t* a32l = (const uint32_t*)pAl;
            #pragma unroll
            for (int j = 0; j < 8; j++) {
                Ash[ahalf * 8 + j][arow] = a32h[j];
                Asl[ahalf * 8 + j][arow] = a32l[j];
            }
            #pragma unroll
            for (int p = 0; p < 4; p++) {
                int kp = p * 4 + kq;
                uint32_t h0 = prmt(pBh[p][0], pBh[p][1], 0x5410);
                uint32_t h1 = prmt(pBh[p][0], pBh[p][1], 0x7632);
                uint32_t l0 = prmt(pBl[p][0], pBl[p][1], 0x5410);
                uint32_t l1 = prmt(pBl[p][0], pBl[p][1], 0x7632);
                *(uint2*)&Bsh[kp][2 * np] = make_uint2(h0, h1);
                *(uint2*)&Bsl[kp][2 * np] = make_uint2(l0, l1);
            }
        }
        __syncthreads();

        // prefetch next chunk (overlaps with MMA below)
        if (c < 15) {
            int k0 = (c + 1) * 32;
            int u4 = k0 / 8 + ahalf * 2;
            pAh[0] = AgH[u4]; pAh[1] = AgH[u4 + 1];
            pAl[0] = AgL[u4]; pAl[1] = AgL[u4 + 1];
            #pragma unroll
            for (int p = 0; p < 4; p++) {
                int kr = k0 + 2 * (p * 4 + kq);
                const uint32_t* r0h = (const uint32_t*)(Bh_g + (size_t)kr * NCOLS) + bn * 64;
                const uint32_t* r1h = (const uint32_t*)(Bh_g + (size_t)(kr + 1) * NCOLS) + bn * 64;
                const uint32_t* r0l = (const uint32_t*)(Bl_g + (size_t)kr * NCOLS) + bn * 64;
                const uint32_t* r1l = (const uint32_t*)(Bl_g + (size_t)(kr + 1) * NCOLS) + bn * 64;
                pBh[p][0] = r0h[np]; pBh[p][1] = r1h[np];
                pBl[p][0] = r0l[np]; pBl[p][1] = r1l[np];
            }
        }

        #pragma unroll
        for (int ks = 0; ks < 2; ks++) {
            uint32_t ah[4][4], al[4][4], bh[4][2], bl[4][2];
            #pragma unroll
            for (int i = 0; i < 4; i++) {
                int m0 = wm + i * 16;
                ah[i][0] = Ash[ks * 8 + t4][m0 + g];
                ah[i][1] = Ash[ks * 8 + t4][m0 + g + 8];
                ah[i][2] = Ash[ks * 8 + 4 + t4][m0 + g];
                ah[i][3] = Ash[ks * 8 + 4 + t4][m0 + g + 8];
                al[i][0] = Asl[ks * 8 + t4][m0 + g];
                al[i][1] = Asl[ks * 8 + t4][m0 + g + 8];
                al[i][2] = Asl[ks * 8 + 4 + t4][m0 + g];
                al[i][3] = Asl[ks * 8 + 4 + t4][m0 + g + 8];
            }
            #pragma unroll
            for (int j = 0; j < 4; j++) {
                int n0 = wn + j * 8;
                bh[j][0] = Bsh[ks * 8 + t4][n0 + g];
                bh[j][1] = Bsh[ks * 8 + 4 + t4][n0 + g];
                bl[j][0] = Bsl[ks * 8 + t4][n0 + g];
                bl[j][1] = Bsl[ks * 8 + 4 + t4][n0 + g];
            }
            #pragma unroll
            for (int i = 0; i < 4; i++)
                #pragma unroll
                for (int j = 0; j < 4; j++) {
                    hmma(acc[i][j], al[i], bh[j]);
                    hmma(acc[i][j], ah[i], bl[j]);
                    hmma(acc[i][j], ah[i], bh[j]);
                }
        }
    }

    // epilogue
    #pragma unroll
    for (int i = 0; i < 4; i++) {
        int row0 = bm * 128 + wm + i * 16 + g;
        int row1 = row0 + 8;
        float bv0 = bias[row0], bv1 = bias[row1];
        #pragma unroll
        for (int j = 0; j < 4; j++) {
            int col = bn * 128 + wn + j * 8 + 2 * t4;
            if (mode == 0) {
                ((uint32_t*)(g_q + (size_t)row0 * NCOLS))[col >> 1] =
                    packf2(acc[i][j][0] + bv0, acc[i][j][1] + bv0);
                ((uint32_t*)(g_q + (size_t)row1 * NCOLS))[col >> 1] =
                    packf2(acc[i][j][2] + bv1, acc[i][j][3] + bv1);
            } else {
                int bb = col >> 10, n = col & 1023;
                size_t i0 = (size_t)bb * CCH * NSEQ + (size_t)row0 * NSEQ + n;
                size_t i1 = (size_t)bb * CCH * NSEQ + (size_t)row1 * NSEQ + n;
                float2 r0 = *(const float2*)(resid + i0);
                float2 r1 = *(const float2*)(resid + i1);
                float2 o0, o1;
                o0.x = acc[i][j][0] + bv0 + r0.x; o0.y = acc[i][j][1] + bv0 + r0.y;
                o1.x = acc[i][j][2] + bv1 + r1.x; o1.y = acc[i][j][3] + bv1 + r1.y;
                *(float2*)(outP + i0) = o0;
                *(float2*)(outP + i1) = o1;
            }
        }
    }
}

// ---------------------------------------------------------------------------
// Flash attention, fp16 m16n8k16. Block 256 thr (8 warps) = (b, h, 128 q).
// Kt[m][dpair] (transposed, packed u32), Vs[d][mpair] (direct u32 copy).
// P A-fragment == adjacent S C-fragments on the same lane: no shuffles.
// ---------------------------------------------------------------------------
__global__ void __launch_bounds__(256) attn_kernel() {
    const int b = blockIdx.z, h = blockIdx.y, qt = blockIdx.x;
    const int tid = threadIdx.x;
    const int w = tid >> 5, lane = tid & 31;
    const int g = lane >> 2, t4 = lane & 3;

    __shared__ uint32_t smem[64 * 34 + 64 * 36];   // 17.9 KB
    uint32_t (*Kt)[34] = (uint32_t(*)[34])smem;            // [m][dp]
    uint32_t (*Vs)[36] = (uint32_t(*)[36])(smem + 64 * 34); // [d][mp]
    uint32_t (*Qt)[34] = (uint32_t(*)[34])smem;            // temp overlay [q][dp]

    const __half* Qb = g_q + (size_t)(h * HD)           * NCOLS + b * NSEQ;
    const __half* Kb = g_q + (size_t)(CCH + h * HD)     * NCOLS + b * NSEQ;
    const __half* Vb = g_q + (size_t)(2 * CCH + h * HD) * NCOLS + b * NSEQ;
    const int qbase = qt * 128;

    // stage Q transposed into smem, then read persistent fragments
    #pragma unroll
    for (int p = 0; p < 16; p++) {
        int idx = p * 256 + tid;
        int qr = idx & 127, dp = idx >> 7;
        __half lo = Qb[(size_t)(2 * dp) * NCOLS + qbase + qr];
        __half hi = Qb[(size_t)(2 * dp + 1) * NCOLS + qbase + qr];
        Qt[qr][dp] = pack2(lo, hi);
    }
    __syncthreads();
    uint32_t qa[4][4];
    {
        const int q0 = w * 16 + g;
        #pragma unroll
        for (int ks = 0; ks < 4; ks++) {
            qa[ks][0] = Qt[q0][ks * 8 + t4];
            qa[ks][1] = Qt[q0 + 8][ks * 8 + t4];
            qa[ks][2] = Qt[q0][ks * 8 + 4 + t4];
            qa[ks][3] = Qt[q0 + 8][ks * 8 + 4 + t4];
        }
    }

    float Ov[8][4];
    #pragma unroll
    for (int dc = 0; dc < 8; dc++)
        #pragma unroll
        for (int r = 0; r < 4; r++) Ov[dc][r] = 0.f;
    float m0 = -1e30f, m1 = -1e30f, l0 = 0.f, l1 = 0.f;

    for (int kt = 0; kt < NSEQ / 64; kt++) {
        const int mbase = kt * 64;
        __syncthreads();
        // K tile transposed: Kt[m][dp] = (K[2dp][m], K[2dp+1][m])
        #pragma unroll
        for (int p = 0; p < 8; p++) {
            int idx = p * 256 + tid;
            int m = idx & 63, dp = idx >> 6;
            __half lo = Kb[(size_t)(2 * dp) * NCOLS + mbase + m];
            __half hi = Kb[(size_t)(2 * dp + 1) * NCOLS + mbase + m];
            Kt[m][dp] = pack2(lo, hi);
        }
        // V tile: direct u32 copy, Vs[d][mp] = (V[d][2mp], V[d][2mp+1])
        #pragma unroll
        for (int p = 0; p < 8; p++) {
            int idx = p * 256 + tid;
            int mp = idx & 31, d = idx >> 5;
            Vs[d][mp] = *((const uint32_t*)(Vb + (size_t)d * NCOLS + mbase) + mp);
        }
        __syncthreads();

        // S = Q K^T  (16q x 64m per warp), then scale
        float Csc[8][4];
        #pragma unroll
        for (int mc = 0; mc < 8; mc++) {
            #pragma unroll
            for (int r = 0; r < 4; r++) Csc[mc][r] = 0.f;
            #pragma unroll
            for (int ks = 0; ks < 4; ks++) {
                uint32_t bb[2];
                bb[0] = Kt[mc * 8 + g][ks * 8 + t4];
                bb[1] = Kt[mc * 8 + g][ks * 8 + 4 + t4];
                hmma(Csc[mc], qa[ks], bb);
            }
            #pragma unroll
            for (int r = 0; r < 4; r++) Csc[mc][r] *= 0.125f;
        }

        // online softmax (rows g, g+8)
        float mx0 = m0, mx1 = m1;
        #pragma unroll
        for (int j = 0; j < 8; j++) {
            mx0 = fmaxf(mx0, fmaxf(Csc[j][0], Csc[j][1]));
            mx1 = fmaxf(mx1, fmaxf(Csc[j][2], Csc[j][3]));
        }
        mx0 = fmaxf(mx0, __shfl_xor_sync(0xffffffffu, mx0, 1));
        mx0 = fmaxf(mx0, __shfl_xor_sync(0xffffffffu, mx0, 2));
        mx1 = fmaxf(mx1, __shfl_xor_sync(0xffffffffu, mx1, 1));
        mx1 = fmaxf(mx1, __shfl_xor_sync(0xffffffffu, mx1, 2));
        float f0 = __expf(m0 - mx0), f1 = __expf(m1 - mx1);
        m0 = mx0; m1 = mx1;
        l0 *= f0; l1 *= f1;
        #pragma unroll
        for (int dc = 0; dc < 8; dc++) {
            Ov[dc][0] *= f0; Ov[dc][1] *= f0;
            Ov[dc][2] *= f1; Ov[dc][3] *= f1;
        }

        float s0 = 0.f, s1 = 0.f;
        #pragma unroll
        for (int j = 0; j < 8; j++) {
            Csc[j][0] = __expf(Csc[j][0] - mx0);
            Csc[j][1] = __expf(Csc[j][1] - mx0);
            Csc[j][2] = __expf(Csc[j][2] - mx1);
            Csc[j][3] = __expf(Csc[j][3] - mx1);
            s0 += Csc[j][0] + Csc[j][1];
            s1 += Csc[j][2] + Csc[j][3];
        }
        s0 += __shfl_xor_sync(0xffffffffu, s0, 1);
        s0 += __shfl_xor_sync(0xffffffffu, s0, 2);
        s1 += __shfl_xor_sync(0xffffffffu, s1, 1);
        s1 += __shfl_xor_sync(0xffffffffu, s1, 2);
        l0 += s0; l1 += s1;

        // P fragments: direct pack, no shuffles
        uint32_t pa[4][4];
        #pragma unroll
        for (int ks = 0; ks < 4; ks++) {
            pa[ks][0] = packf2(Csc[2 * ks][0],     Csc[2 * ks][1]);
            pa[ks][1] = packf2(Csc[2 * ks][2],     Csc[2 * ks][3]);
            pa[ks][2] = packf2(Csc[2 * ks + 1][0], Csc[2 * ks + 1][1]);
            pa[ks][3] = packf2(Csc[2 * ks + 1][2], Csc[2 * ks + 1][3]);
        }

        // O += P V
        #pragma unroll
        for (int dc = 0; dc < 8; dc++) {
            #pragma unroll
            for (int ks = 0; ks < 4; ks++) {
                uint32_t bb[2];
                bb[0] = Vs[dc * 8 + g][ks * 8 + t4];
                bb[1] = Vs[dc * 8 + g][ks * 8 + 4 + t4];
                hmma(Ov[dc], pa[ks], bb);
            }
        }
    }

    // write O hi/lo to g_oh/g_ol [C][B*N]
    float inv0 = 1.f / l0, inv1 = 1.f / l1;
    const int q0 = qbase + w * 16 + g;
    #pragma unroll
    for (int dc = 0; dc < 8; dc++) {
        #pragma unroll
        for (int p = 0; p < 2; p++) {
            int d = dc * 8 + 2 * t4 + p;
            size_t base = (size_t)(h * HD + d) * NCOLS + b * NSEQ;
            float v0 = Ov[dc][p] * inv0;       // row q0
            float v1 = Ov[dc][2 + p] * inv1;   // row q0+8
            __half h0, l0h, h1, l1h;
            hsplit(v0, h0, l0h); hsplit(v1, h1, l1h);
            g_oh[base + q0]     = h0; g_ol[base + q0]     = l0h;
            g_oh[base + q0 + 8] = h1; g_ol[base + q0 + 8] = l1h;
        }
    }
}

// ---------------------------------------------------------------------------
extern "C" void kernel_launch(void* const* d_in, const int* in_sizes, int n_in,
                              void* d_out, int out_size) {
    const float* x      = (const float*)d_in[0];
    const float* gn_w   = (const float*)d_in[1];
    const float* gn_b   = (const float*)d_in[2];
    const float* qkv_w  = (const float*)d_in[3];
    const float* qkv_b  = (const float*)d_in[4];
    const float* proj_w = (const float*)d_in[5];
    const float* proj_b = (const float*)d_in[6];
    float* out = (float*)d_out;

    gn_kernel<<<BATCH * NGRP, 256>>>(x, gn_w, gn_b);
    prep_w_kernel<<<512, 256>>>(qkv_w, proj_w);

    gemm_kernel<<<dim3(NCOLS / 128, (3 * CCH) / 128), 256>>>(
        qkv_b, nullptr, nullptr, 0);

    attn_kernel<<<dim3(NSEQ / 128, NH, BATCH), 256>>>();

    gemm_kernel<<<dim3(NCOLS / 128, CCH / 128), 256>>>(
        proj_b, out, x, 1);
}

// round 6
// speedup vs baseline: 5.9460x; 2.1087x over previous
#include <cuda_runtime.h>
#include <cuda_fp16.h>
#include <math.h>
#include <stdint.h>

#define BATCH 8
#define CCH   512
#define NSEQ  1024
#define NCOLS 8192
#define NH    8
#define HD    64
#define NGRP  32
#define QW_ELEMS (3 * CCH * CCH)
#define PW_ELEMS (CCH * CCH)

__device__ __half g_xh[CCH * NCOLS];       // xn (half), [C][B*N]
__device__ __half g_wh[QW_ELEMS];          // qkv_w half
__device__ __half g_ph[PW_ELEMS];          // proj_w half
__device__ __half g_q [3 * CCH * NCOLS];   // qkv, [3C][B*N]
__device__ __half g_oh[CCH * NCOLS];       // attention out, [C][B*N]

// ---------------- helpers ----------------
__device__ __forceinline__ uint32_t packf2(float lo, float hi) {
    __half2 p = __floats2half2_rn(lo, hi);
    return *reinterpret_cast<uint32_t*>(&p);
}
__device__ __forceinline__ void hmma(float c[4], const uint32_t a[4], const uint32_t b[2]) {
    asm volatile(
        "mma.sync.aligned.m16n8k16.row.col.f32.f16.f16.f32 "
        "{%0,%1,%2,%3}, {%4,%5,%6,%7}, {%8,%9}, {%0,%1,%2,%3};"
        : "+f"(c[0]), "+f"(c[1]), "+f"(c[2]), "+f"(c[3])
        : "r"(a[0]), "r"(a[1]), "r"(a[2]), "r"(a[3]), "r"(b[0]), "r"(b[1]));
}
__device__ __forceinline__ void ldsm4(uint32_t r[4], uint32_t addr) {
    asm volatile("ldmatrix.sync.aligned.m8n8.x4.shared.b16 {%0,%1,%2,%3}, [%4];"
        : "=r"(r[0]), "=r"(r[1]), "=r"(r[2]), "=r"(r[3]) : "r"(addr));
}
__device__ __forceinline__ void ldsm4t(uint32_t r[4], uint32_t addr) {
    asm volatile("ldmatrix.sync.aligned.m8n8.x4.trans.shared.b16 {%0,%1,%2,%3}, [%4];"
        : "=r"(r[0]), "=r"(r[1]), "=r"(r[2]), "=r"(r[3]) : "r"(addr));
}
__device__ __forceinline__ void cpa16(uint32_t dst, const void* src) {
    asm volatile("cp.async.cg.shared.global [%0], [%1], 16;" :: "r"(dst), "l"(src));
}
__device__ __forceinline__ void cp_commit() { asm volatile("cp.async.commit_group;" ::); }
__device__ __forceinline__ void cp_wait0() { asm volatile("cp.async.wait_group 0;" ::); }
__device__ __forceinline__ void cp_wait1() { asm volatile("cp.async.wait_group 1;" ::); }
__device__ __forceinline__ float ex2(float x) {
    float y; asm("ex2.approx.f32 %0, %1;" : "=f"(y) : "f"(x)); return y;
}

// ---------------------------------------------------------------------------
// GroupNorm: writes xn (half) transposed [C][B*N]
// ---------------------------------------------------------------------------
__global__ void __launch_bounds__(256) gn_kernel(const float* __restrict__ x,
                                                 const float* __restrict__ gw,
                                                 const float* __restrict__ gb) {
    int bg = blockIdx.x;
    int b = bg >> 5, g = bg & 31;
    const float* xp = x + (size_t)b * CCH * NSEQ + (size_t)g * 16 * NSEQ;

    float s = 0.f, s2 = 0.f;
    for (int i = threadIdx.x; i < 4096; i += 256) {
        float4 v = ((const float4*)xp)[i];
        s  += v.x + v.y + v.z + v.w;
        s2 += v.x*v.x + v.y*v.y + v.z*v.z + v.w*v.w;
    }
    #pragma unroll
    for (int o = 16; o > 0; o >>= 1) {
        s  += __shfl_xor_sync(0xffffffffu, s,  o);
        s2 += __shfl_xor_sync(0xffffffffu, s2, o);
    }
    __shared__ float rs[8], rs2[8];
    if ((threadIdx.x & 31) == 0) { rs[threadIdx.x >> 5] = s; rs2[threadIdx.x >> 5] = s2; }
    __syncthreads();
    float tot = 0.f, tot2 = 0.f;
    #pragma unroll
    for (int i = 0; i < 8; i++) { tot += rs[i]; tot2 += rs2[i]; }
    float mean = tot * (1.f / 16384.f);
    float var  = tot2 * (1.f / 16384.f) - mean * mean;
    float rstd = rsqrtf(var + 1e-5f);

    for (int i = threadIdx.x; i < 4096; i += 256) {
        int c = g * 16 + (i >> 8);
        float4 v = ((const float4*)xp)[i];
        float wch = gw[c] * rstd;
        float bch = gb[c] - mean * wch;
        uint32_t* oh = (uint32_t*)(g_xh + (size_t)c * NCOLS + (size_t)b * NSEQ);
        int j = (i & 255) * 2;
        oh[j]     = packf2(v.x * wch + bch, v.y * wch + bch);
        oh[j + 1] = packf2(v.z * wch + bch, v.w * wch + bch);
    }
}

// ---------------------------------------------------------------------------
// Weight convert: qkv_w, proj_w -> half
// ---------------------------------------------------------------------------
__global__ void __launch_bounds__(256) prep_w_kernel(const float* __restrict__ qw,
                                                     const float* __restrict__ pw) {
    const int total4 = (QW_ELEMS + PW_ELEMS) / 4;
    for (int i = blockIdx.x * 256 + threadIdx.x; i < total4; i += gridDim.x * 256) {
        float4 v;
        uint32_t* dst;
        if (i < QW_ELEMS / 4) {
            v = ((const float4*)qw)[i];
            dst = (uint32_t*)(g_wh + 4 * (size_t)i);
        } else {
            int j = i - QW_ELEMS / 4;
            v = ((const float4*)pw)[j];
            dst = (uint32_t*)(g_ph + 4 * (size_t)j);
        }
        dst[0] = packf2(v.x, v.y);
        dst[1] = packf2(v.z, v.w);
    }
}

// ---------------------------------------------------------------------------
// fp16 GEMM: C[M x 8192] = A[M x 512] * B[512 x 8192]  (+bias, +resid)
// A half [m][k] row-major; B half [k][n]. Smem: As[m 128][kp 16] stride 20,
// Bs[k 32][np 64] stride 68. ldmatrix frags, cp.async double buffer, kchunk 32.
// mode 0: A=g_wh, B=g_xh, C=g_q (half). mode 1: A=g_ph, B=g_oh, C=out+resid.
// ---------------------------------------------------------------------------
__global__ void __launch_bounds__(256) gemm_kernel(const float* __restrict__ bias,
                                                   float* __restrict__ outP,
                                                   const float* __restrict__ resid,
                                                   int mode) {
    const __half* Ag = mode ? g_ph : g_wh;
    const __half* Bg = mode ? g_oh : g_xh;

    __shared__ __align__(16) uint32_t As[2][128 * 20];
    __shared__ __align__(16) uint32_t Bs[2][32 * 68];

    const int bm = blockIdx.y, bn = blockIdx.x;
    const int tid = threadIdx.x;
    const int w = tid >> 5, lane = tid & 31;
    const int g = lane >> 2, t4 = lane & 3;
    const int r = lane & 7, jm = lane >> 3;
    const int wm = (w >> 2) * 64;
    const int wn = (w & 3) * 32;

    const uint32_t sA0 = (uint32_t)__cvta_generic_to_shared(&As[0][0]);
    const uint32_t sA1 = (uint32_t)__cvta_generic_to_shared(&As[1][0]);
    const uint32_t sB0 = (uint32_t)__cvta_generic_to_shared(&Bs[0][0]);
    const uint32_t sB1 = (uint32_t)__cvta_generic_to_shared(&Bs[1][0]);

    // staging maps
    const int am = tid >> 1, ac = tid & 1;                 // A: row, 2 chunks
    const char* aSrc = (const char*)(Ag + (size_t)(bm * 128 + am) * CCH);
    const uint32_t aDst = am * 20 + ac * 4;
    const int bk = tid >> 3, bc = tid & 7;                 // B: row, 2 chunks
    const uint32_t bDst = bk * 68 + bc * 4;

    // frag address lane parts
    const uint32_t aPart = (8 * (jm & 1) + r) * 20 + 4 * (jm >> 1);
    const uint32_t bPart = (8 * (jm & 1) + r) * 68 + (wn >> 1) + 4 * (jm >> 1);

    float acc[4][4][4];
    #pragma unroll
    for (int i = 0; i < 4; i++)
        #pragma unroll
        for (int j = 0; j < 4; j++)
            #pragma unroll
            for (int q = 0; q < 4; q++) acc[i][j][q] = 0.f;

    // prologue: stage chunk 0
    {
        uint32_t ab = (uint32_t)__cvta_generic_to_shared(&As[0][0]);
        uint32_t bb_ = (uint32_t)__cvta_generic_to_shared(&Bs[0][0]);
        cpa16(ab + (aDst) * 4,            aSrc + ac * 16);
        cpa16(ab + (aDst + 8) * 4,        aSrc + ac * 16 + 32);
        const char* bSrc = (const char*)(Bg + (size_t)bk * NCOLS + bn * 128);
        cpa16(bb_ + (bDst) * 4,           bSrc + bc * 16);
        cpa16(bb_ + (bDst + 32) * 4,      bSrc + bc * 16 + 128);
        cp_commit();
    }

    for (int c = 0; c < 16; c++) {
        __syncthreads();
        if (c < 15) {
            int k0 = (c + 1) * 32;
            uint32_t ab = (c + 1) & 1 ? sA1 : sA0;
            uint32_t bb_ = (c + 1) & 1 ? sB1 : sB0;
            cpa16(ab + (aDst) * 4,        aSrc + k0 * 2 + ac * 16);
            cpa16(ab + (aDst + 8) * 4,    aSrc + k0 * 2 + ac * 16 + 32);
            const char* bSrc = (const char*)(Bg + (size_t)(k0 + bk) * NCOLS + bn * 128);
            cpa16(bb_ + (bDst) * 4,       bSrc + bc * 16);
            cpa16(bb_ + (bDst + 32) * 4,  bSrc + bc * 16 + 128);
            cp_commit();
            cp_wait1();
        } else {
            cp_wait0();
        }
        __syncthreads();

        const uint32_t aB = (c & 1) ? sA1 : sA0;
        const uint32_t bB = (c & 1) ? sB1 : sB0;
        #pragma unroll
        for (int ks = 0; ks < 2; ks++) {
            uint32_t afr[4][4], bfr[4][2];
            #pragma unroll
            for (int i = 0; i < 4; i++)
                ldsm4(afr[i], aB + ((wm + i * 16) * 20 + ks * 8 + aPart) * 4);
            #pragma unroll
            for (int jp = 0; jp < 2; jp++) {
                uint32_t rr[4];
                ldsm4t(rr, bB + (16 * ks * 68 + 8 * jp + bPart) * 4);
                bfr[2 * jp][0] = rr[0]; bfr[2 * jp][1] = rr[1];
                bfr[2 * jp + 1][0] = rr[2]; bfr[2 * jp + 1][1] = rr[3];
            }
            #pragma unroll
            for (int i = 0; i < 4; i++)
                #pragma unroll
                for (int j = 0; j < 4; j++)
                    hmma(acc[i][j], afr[i], bfr[j]);
        }
    }

    // epilogue
    #pragma unroll
    for (int i = 0; i < 4; i++) {
        int row0 = bm * 128 + wm + i * 16 + g;
        int row1 = row0 + 8;
        float bv0 = bias[row0], bv1 = bias[row1];
        #pragma unroll
        for (int j = 0; j < 4; j++) {
            int col = bn * 128 + wn + j * 8 + 2 * t4;
            if (mode == 0) {
                ((uint32_t*)(g_q + (size_t)row0 * NCOLS))[col >> 1] =
                    packf2(acc[i][j][0] + bv0, acc[i][j][1] + bv0);
                ((uint32_t*)(g_q + (size_t)row1 * NCOLS))[col >> 1] =
                    packf2(acc[i][j][2] + bv1, acc[i][j][3] + bv1);
            } else {
                int bb = col >> 10, n = col & 1023;
                size_t i0 = (size_t)bb * CCH * NSEQ + (size_t)row0 * NSEQ + n;
                size_t i1 = (size_t)bb * CCH * NSEQ + (size_t)row1 * NSEQ + n;
                float2 r0 = *(const float2*)(resid + i0);
                float2 r1 = *(const float2*)(resid + i1);
                float2 o0, o1;
                o0.x = acc[i][j][0] + bv0 + r0.x; o0.y = acc[i][j][1] + bv0 + r0.y;
                o1.x = acc[i][j][2] + bv1 + r1.x; o1.y = acc[i][j][3] + bv1 + r1.y;
                *(float2*)(outP + i0) = o0;
                *(float2*)(outP + i1) = o1;
            }
        }
    }
}

// ---------------------------------------------------------------------------
// Flash attention, fp16 mma + ldmatrix + cp.async double buffer.
// Block 256 thr (8 warps) = (b, h, 128 q); warp = 16 q rows.
// K/V tiles staged as direct u32 copies [d 64][m-pairs 32] stride 36.
// S B-frags via ldmatrix.trans, PV B-frags via ldmatrix. ex2 softmax.
// ---------------------------------------------------------------------------
__global__ void __launch_bounds__(256) attn_kernel() {
    const int b = blockIdx.z, h = blockIdx.y, qt = blockIdx.x;
    const int tid = threadIdx.x;
    const int w = tid >> 5, lane = tid & 31;
    const int g = lane >> 2, t4 = lane & 3;
    const int r = lane & 7, jm = lane >> 3;

    __shared__ __align__(16) uint32_t sm[2][2 * 64 * 36];  // per buf: K then V

    const __half* Qb = g_q + (size_t)(h * HD)           * NCOLS + b * NSEQ;
    const __half* Kb = g_q + (size_t)(CCH + h * HD)     * NCOLS + b * NSEQ;
    const __half* Vb = g_q + (size_t)(2 * CCH + h * HD) * NCOLS + b * NSEQ;
    const int qbase = qt * 128;

    const uint32_t s0 = (uint32_t)__cvta_generic_to_shared(&sm[0][0]);
    const uint32_t s1 = (uint32_t)__cvta_generic_to_shared(&sm[1][0]);

    // ---- stage Q [d][qp] stride 68 into sm[0] region, extract frags ----
    {
        uint32_t* q32 = &sm[0][0];
        #pragma unroll
        for (int p = 0; p < 16; p++) {
            int idx = p * 256 + tid;
            int d = idx >> 6, qp = idx & 63;
            q32[d * 68 + qp] = ((const uint32_t*)(Qb + (size_t)d * NCOLS + qbase))[qp];
        }
    }
    __syncthreads();
    uint32_t qa[4][4];
    {
        const uint32_t qPart = (w * 8 + 4 * (jm & 1) + (16 * 0)) ; // col part
        #pragma unroll
        for (int ks = 0; ks < 4; ks++) {
            uint32_t off = (16 * ks + 8 * (jm >> 1) + r) * 68 + w * 8 + 4 * (jm & 1);
            ldsm4t(qa[ks], s0 + off * 4);
        }
        (void)qPart;
    }
    __syncthreads();

    // staging lane map (4 x cp16 per tile)
    const int sd = tid >> 3, sch = tid & 7;   // covers idx = tid and tid+256
    const int sd2 = (256 + tid) >> 3;

    // frag lane parts
    const uint32_t kPart = (8 * (jm & 1) + r) * 36 + 4 * (jm >> 1);   // + 16ks*36 + 8p... wait p term
    const uint32_t vPart = ((jm >> 1) * 8 + r) * 36 + 4 * (jm & 1);

    // prologue: stage tile 0 into buf 0
    {
        const char* ksrc = (const char*)(Kb + (size_t)sd * NCOLS);
        const char* ksrc2 = (const char*)(Kb + (size_t)sd2 * NCOLS);
        const char* vsrc = (const char*)(Vb + (size_t)sd * NCOLS);
        const char* vsrc2 = (const char*)(Vb + (size_t)sd2 * NCOLS);
        cpa16(s0 + (sd * 36 + sch * 4) * 4,                ksrc + sch * 16);
        cpa16(s0 + (sd2 * 36 + sch * 4) * 4,               ksrc2 + sch * 16);
        cpa16(s0 + (2304 + sd * 36 + sch * 4) * 4,         vsrc + sch * 16);
        cpa16(s0 + (2304 + sd2 * 36 + sch * 4) * 4,        vsrc2 + sch * 16);
        cp_commit();
    }

    float Ov[8][4];
    #pragma unroll
    for (int dc = 0; dc < 8; dc++)
        #pragma unroll
        for (int q = 0; q < 4; q++) Ov[dc][q] = 0.f;
    float m0 = -1e30f, m1 = -1e30f, l0 = 0.f, l1 = 0.f;
    const float SC = 0.125f * 1.4426950408889634f;

    for (int kt = 0; kt < NSEQ / 64; kt++) {
        __syncthreads();
        if (kt < 15) {
            const int mb = (kt + 1) * 64;
            uint32_t sb = ((kt + 1) & 1) ? s1 : s0;
            const char* ksrc = (const char*)(Kb + (size_t)sd * NCOLS + mb);
            const char* ksrc2 = (const char*)(Kb + (size_t)sd2 * NCOLS + mb);
            const char* vsrc = (const char*)(Vb + (size_t)sd * NCOLS + mb);
            const char* vsrc2 = (const char*)(Vb + (size_t)sd2 * NCOLS + mb);
            cpa16(sb + (sd * 36 + sch * 4) * 4,         ksrc + sch * 16);
            cpa16(sb + (sd2 * 36 + sch * 4) * 4,        ksrc2 + sch * 16);
            cpa16(sb + (2304 + sd * 36 + sch * 4) * 4,  vsrc + sch * 16);
            cpa16(sb + (2304 + sd2 * 36 + sch * 4) * 4, vsrc2 + sch * 16);
            cp_commit();
            cp_wait1();
        } else {
            cp_wait0();
        }
        __syncthreads();

        const uint32_t kB = (kt & 1) ? s1 : s0;
        const uint32_t vB = kB + 2304 * 4;

        // S = Q K^T
        float Csc[8][4];
        #pragma unroll
        for (int mc = 0; mc < 8; mc++)
            #pragma unroll
            for (int q = 0; q < 4; q++) Csc[mc][q] = 0.f;
        #pragma unroll
        for (int p = 0; p < 4; p++) {
            #pragma unroll
            for (int ks = 0; ks < 4; ks++) {
                uint32_t rr[4];
                ldsm4t(rr, kB + (16 * ks * 36 + 8 * p + kPart) * 4);
                hmma(Csc[2 * p],     qa[ks], rr);
                hmma(Csc[2 * p + 1], qa[ks], rr + 2);
            }
        }
        #pragma unroll
        for (int mc = 0; mc < 8; mc++)
            #pragma unroll
            for (int q = 0; q < 4; q++) Csc[mc][q] *= SC;

        // online softmax (base-2 domain)
        float mx0 = m0, mx1 = m1;
        #pragma unroll
        for (int j = 0; j < 8; j++) {
            mx0 = fmaxf(mx0, fmaxf(Csc[j][0], Csc[j][1]));
            mx1 = fmaxf(mx1, fmaxf(Csc[j][2], Csc[j][3]));
        }
        mx0 = fmaxf(mx0, __shfl_xor_sync(0xffffffffu, mx0, 1));
        mx0 = fmaxf(mx0, __shfl_xor_sync(0xffffffffu, mx0, 2));
        mx1 = fmaxf(mx1, __shfl_xor_sync(0xffffffffu, mx1, 1));
        mx1 = fmaxf(mx1, __shfl_xor_sync(0xffffffffu, mx1, 2));
        float f0 = ex2(m0 - mx0), f1 = ex2(m1 - mx1);
        m0 = mx0; m1 = mx1;
        l0 *= f0; l1 *= f1;
        #pragma unroll
        for (int dc = 0; dc < 8; dc++) {
            Ov[dc][0] *= f0; Ov[dc][1] *= f0;
            Ov[dc][2] *= f1; Ov[dc][3] *= f1;
        }

        float ss0 = 0.f, ss1 = 0.f;
        #pragma unroll
        for (int j = 0; j < 8; j++) {
            Csc[j][0] = ex2(Csc[j][0] - mx0);
            Csc[j][1] = ex2(Csc[j][1] - mx0);
            Csc[j][2] = ex2(Csc[j][2] - mx1);
            Csc[j][3] = ex2(Csc[j][3] - mx1);
            ss0 += Csc[j][0] + Csc[j][1];
            ss1 += Csc[j][2] + Csc[j][3];
        }
        ss0 += __shfl_xor_sync(0xffffffffu, ss0, 1);
        ss0 += __shfl_xor_sync(0xffffffffu, ss0, 2);
        ss1 += __shfl_xor_sync(0xffffffffu, ss1, 1);
        ss1 += __shfl_xor_sync(0xffffffffu, ss1, 2);
        l0 += ss0; l1 += ss1;

        // P A-frags: direct pack from C-frags
        uint32_t pa[4][4];
        #pragma unroll
        for (int ks = 0; ks < 4; ks++) {
            pa[ks][0] = packf2(Csc[2 * ks][0],     Csc[2 * ks][1]);
            pa[ks][1] = packf2(Csc[2 * ks][2],     Csc[2 * ks][3]);
            pa[ks][2] = packf2(Csc[2 * ks + 1][0], Csc[2 * ks + 1][1]);
            pa[ks][3] = packf2(Csc[2 * ks + 1][2], Csc[2 * ks + 1][3]);
        }

        // O += P V
        #pragma unroll
        for (int dcp = 0; dcp < 4; dcp++) {
            #pragma unroll
            for (int ks = 0; ks < 4; ks++) {
                uint32_t rr[4];
                ldsm4(rr, vB + ((2 * dcp) * 8 * 36 + 8 * ks + vPart) * 4);
                hmma(Ov[2 * dcp],     pa[ks], rr);
                hmma(Ov[2 * dcp + 1], pa[ks], rr + 2);
            }
        }
    }

    // write O (half) to g_oh [C][B*N]
    float inv0 = 1.f / l0, inv1 = 1.f / l1;
    const int q0 = qbase + w * 16 + g;
    #pragma unroll
    for (int dc = 0; dc < 8; dc++) {
        #pragma unroll
        for (int p = 0; p < 2; p++) {
            int d = dc * 8 + 2 * t4 + p;
            __half* base = g_oh + (size_t)(h * HD + d) * NCOLS + b * NSEQ;
            base[q0]     = __float2half_rn(Ov[dc][p] * inv0);
            base[q0 + 8] = __float2half_rn(Ov[dc][2 + p] * inv1);
        }
    }
}

// ---------------------------------------------------------------------------
extern "C" void kernel_launch(void* const* d_in, const int* in_sizes, int n_in,
                              void* d_out, int out_size) {
    const float* x      = (const float*)d_in[0];
    const float* gn_w   = (const float*)d_in[1];
    const float* gn_b   = (const float*)d_in[2];
    const float* qkv_w  = (const float*)d_in[3];
    const float* qkv_b  = (const float*)d_in[4];
    const float* proj_w = (const float*)d_in[5];
    const float* proj_b = (const float*)d_in[6];
    float* out = (float*)d_out;

    gn_kernel<<<BATCH * NGRP, 256>>>(x, gn_w, gn_b);
    prep_w_kernel<<<256, 256>>>(qkv_w, proj_w);

    gemm_kernel<<<dim3(NCOLS / 128, (3 * CCH) / 128), 256>>>(
        qkv_b, nullptr, nullptr, 0);

    attn_kernel<<<dim3(NSEQ / 128, NH, BATCH), 256>>>();

    gemm_kernel<<<dim3(NCOLS / 128, CCH / 128), 256>>>(
        proj_b, out, x, 1);
}

// round 8
// speedup vs baseline: 6.0082x; 1.0105x over previous
#include <cuda_runtime.h>
#include <cuda_fp16.h>
#include <math.h>
#include <stdint.h>

#define BATCH 8
#define CCH   512
#define NSEQ  1024
#define NCOLS 8192
#define NH    8
#define HD    64
#define NGRP  32
#define QW_ELEMS (3 * CCH * CCH)
#define PW_ELEMS (CCH * CCH)
#define SCQ 0.18033688f   // 0.125 * log2(e)

__device__ __half g_xh[CCH * NCOLS];       // xn (half), [C][B*N]
__device__ __half g_wh[QW_ELEMS];          // qkv_w half
__device__ __half g_ph[PW_ELEMS];          // proj_w half
__device__ __half g_q [3 * CCH * NCOLS];   // qkv, [3C][B*N]; Q rows pre-scaled
__device__ __half g_oh[CCH * NCOLS];       // attention out, [C][B*N]

// ---------------- helpers ----------------
__device__ __forceinline__ uint32_t packf2(float lo, float hi) {
    __half2 p = __floats2half2_rn(lo, hi);
    return *reinterpret_cast<uint32_t*>(&p);
}
__device__ __forceinline__ void hmma(float c[4], const uint32_t a[4], const uint32_t b[2]) {
    asm volatile(
        "mma.sync.aligned.m16n8k16.row.col.f32.f16.f16.f32 "
        "{%0,%1,%2,%3}, {%4,%5,%6,%7}, {%8,%9}, {%0,%1,%2,%3};"
        : "+f"(c[0]), "+f"(c[1]), "+f"(c[2]), "+f"(c[3])
        : "r"(a[0]), "r"(a[1]), "r"(a[2]), "r"(a[3]), "r"(b[0]), "r"(b[1]));
}
__device__ __forceinline__ void ldsm4(uint32_t r[4], uint32_t addr) {
    asm volatile("ldmatrix.sync.aligned.m8n8.x4.shared.b16 {%0,%1,%2,%3}, [%4];"
        : "=r"(r[0]), "=r"(r[1]), "=r"(r[2]), "=r"(r[3]) : "r"(addr));
}
__device__ __forceinline__ void ldsm4t(uint32_t r[4], uint32_t addr) {
    asm volatile("ldmatrix.sync.aligned.m8n8.x4.trans.shared.b16 {%0,%1,%2,%3}, [%4];"
        : "=r"(r[0]), "=r"(r[1]), "=r"(r[2]), "=r"(r[3]) : "r"(addr));
}
__device__ __forceinline__ void cpa16(uint32_t dst, const void* src) {
    asm volatile("cp.async.cg.shared.global [%0], [%1], 16;" :: "r"(dst), "l"(src));
}
__device__ __forceinline__ void cp_commit() { asm volatile("cp.async.commit_group;" ::); }
__device__ __forceinline__ void cp_wait0() { asm volatile("cp.async.wait_group 0;" ::); }
__device__ __forceinline__ void cp_wait1() { asm volatile("cp.async.wait_group 1;" ::); }
__device__ __forceinline__ float ex2(float x) {
    float y; asm("ex2.approx.f32 %0, %1;" : "=f"(y) : "f"(x)); return y;
}

// ---------------------------------------------------------------------------
// GroupNorm: writes xn (half) transposed [C][B*N]
// ---------------------------------------------------------------------------
__global__ void __launch_bounds__(256) gn_kernel(const float* __restrict__ x,
                                                 const float* __restrict__ gw,
                                                 const float* __restrict__ gb) {
    int bg = blockIdx.x;
    int b = bg >> 5, g = bg & 31;
    const float* xp = x + (size_t)b * CCH * NSEQ + (size_t)g * 16 * NSEQ;

    float s = 0.f, s2 = 0.f;
    for (int i = threadIdx.x; i < 4096; i += 256) {
        float4 v = ((const float4*)xp)[i];
        s  += v.x + v.y + v.z + v.w;
        s2 += v.x*v.x + v.y*v.y + v.z*v.z + v.w*v.w;
    }
    #pragma unroll
    for (int o = 16; o > 0; o >>= 1) {
        s  += __shfl_xor_sync(0xffffffffu, s,  o);
        s2 += __shfl_xor_sync(0xffffffffu, s2, o);
    }
    __shared__ float rs[8], rs2[8];
    if ((threadIdx.x & 31) == 0) { rs[threadIdx.x >> 5] = s; rs2[threadIdx.x >> 5] = s2; }
    __syncthreads();
    float tot = 0.f, tot2 = 0.f;
    #pragma unroll
    for (int i = 0; i < 8; i++) { tot += rs[i]; tot2 += rs2[i]; }
    float mean = tot * (1.f / 16384.f);
    float var  = tot2 * (1.f / 16384.f) - mean * mean;
    float rstd = rsqrtf(var + 1e-5f);

    for (int i = threadIdx.x; i < 4096; i += 256) {
        int c = g * 16 + (i >> 8);
        float4 v = ((const float4*)xp)[i];
        float wch = gw[c] * rstd;
        float bch = gb[c] - mean * wch;
        uint32_t* oh = (uint32_t*)(g_xh + (size_t)c * NCOLS + (size_t)b * NSEQ);
        int j = (i & 255) * 2;
        oh[j]     = packf2(v.x * wch + bch, v.y * wch + bch);
        oh[j + 1] = packf2(v.z * wch + bch, v.w * wch + bch);
    }
}

// ---------------------------------------------------------------------------
// Weight convert: qkv_w, proj_w -> half
// ---------------------------------------------------------------------------
__global__ void __launch_bounds__(256) prep_w_kernel(const float* __restrict__ qw,
                                                     const float* __restrict__ pw) {
    const int total4 = (QW_ELEMS + PW_ELEMS) / 4;
    for (int i = blockIdx.x * 256 + threadIdx.x; i < total4; i += gridDim.x * 256) {
        float4 v;
        uint32_t* dst;
        if (i < QW_ELEMS / 4) {
            v = ((const float4*)qw)[i];
            dst = (uint32_t*)(g_wh + 4 * (size_t)i);
        } else {
            int j = i - QW_ELEMS / 4;
            v = ((const float4*)pw)[j];
            dst = (uint32_t*)(g_ph + 4 * (size_t)j);
        }
        dst[0] = packf2(v.x, v.y);
        dst[1] = packf2(v.z, v.w);
    }
}

// ---------------------------------------------------------------------------
// fp16 GEMM: C[M x 8192] = A[M x 512] * B[512 x 8192]  (+bias, +resid)
// mode 0: A=g_wh, B=g_xh, C=g_q (half; Q rows pre-scaled by SCQ).
// mode 1: A=g_ph, B=g_oh, C=out+resid.
// __launch_bounds__(256,2): cap regs at 128 so 2 blocks/SM resident.
// ---------------------------------------------------------------------------
__global__ void __launch_bounds__(256, 2) gemm_kernel(const float* __restrict__ bias,
                                                      float* __restrict__ outP,
                                                      const float* __restrict__ resid,
                                                      int mode) {
    const __half* Ag = mode ? g_ph : g_wh;
    const __half* Bg = mode ? g_oh : g_xh;

    __shared__ __align__(16) uint32_t As[2][128 * 20];
    __shared__ __align__(16) uint32_t Bs[2][32 * 68];

    const int bm = blockIdx.y, bn = blockIdx.x;
    const int tid = threadIdx.x;
    const int w = tid >> 5, lane = tid & 31;
    const int g = lane >> 2, t4 = lane & 3;
    const int r = lane & 7, jm = lane >> 3;
    const int wm = (w >> 2) * 64;
    const int wn = (w & 3) * 32;

    const uint32_t sA0 = (uint32_t)__cvta_generic_to_shared(&As[0][0]);
    const uint32_t sA1 = (uint32_t)__cvta_generic_to_shared(&As[1][0]);
    const uint32_t sB0 = (uint32_t)__cvta_generic_to_shared(&Bs[0][0]);
    const uint32_t sB1 = (uint32_t)__cvta_generic_to_shared(&Bs[1][0]);

    const int am = tid >> 1, ac = tid & 1;
    const char* aSrc = (const char*)(Ag + (size_t)(bm * 128 + am) * CCH);
    const uint32_t aDst = am * 20 + ac * 4;
    const int bk = tid >> 3, bc = tid & 7;
    const uint32_t bDst = bk * 68 + bc * 4;

    const uint32_t aPart = (8 * (jm & 1) + r) * 20 + 4 * (jm >> 1);
    const uint32_t bPart = (8 * (jm & 1) + r) * 68 + (wn >> 1) + 4 * (jm >> 1);

    float acc[4][4][4];
    #pragma unroll
    for (int i = 0; i < 4; i++)
        #pragma unroll
        for (int j = 0; j < 4; j++)
            #pragma unroll
            for (int q = 0; q < 4; q++) acc[i][j][q] = 0.f;

    {
        cpa16(sA0 + (aDst) * 4,       aSrc + ac * 16);
        cpa16(sA0 + (aDst + 8) * 4,   aSrc + ac * 16 + 32);
        const char* bSrc = (const char*)(Bg + (size_t)bk * NCOLS + bn * 128);
        cpa16(sB0 + (bDst) * 4,       bSrc + bc * 16);
        cpa16(sB0 + (bDst + 32) * 4,  bSrc + bc * 16 + 128);
        cp_commit();
    }

    for (int c = 0; c < 16; c++) {
        __syncthreads();
        if (c < 15) {
            int k0 = (c + 1) * 32;
            uint32_t ab = (c + 1) & 1 ? sA1 : sA0;
            uint32_t bb_ = (c + 1) & 1 ? sB1 : sB0;
            cpa16(ab + (aDst) * 4,        aSrc + k0 * 2 + ac * 16);
            cpa16(ab + (aDst + 8) * 4,    aSrc + k0 * 2 + ac * 16 + 32);
            const char* bSrc = (const char*)(Bg + (size_t)(k0 + bk) * NCOLS + bn * 128);
            cpa16(bb_ + (bDst) * 4,       bSrc + bc * 16);
            cpa16(bb_ + (bDst + 32) * 4,  bSrc + bc * 16 + 128);
            cp_commit();
            cp_wait1();
        } else {
            cp_wait0();
        }
        __syncthreads();

        const uint32_t aB = (c & 1) ? sA1 : sA0;
        const uint32_t bB = (c & 1) ? sB1 : sB0;
        #pragma unroll
        for (int ks = 0; ks < 2; ks++) {
            uint32_t afr[4][4], bfr[4][2];
            #pragma unroll
            for (int i = 0; i < 4; i++)
                ldsm4(afr[i], aB + ((wm + i * 16) * 20 + ks * 8 + aPart) * 4);
            #pragma unroll
            for (int jp = 0; jp < 2; jp++) {
                uint32_t rr[4];
                ldsm4t(rr, bB + (16 * ks * 68 + 8 * jp + bPart) * 4);
                bfr[2 * jp][0] = rr[0]; bfr[2 * jp][1] = rr[1];
                bfr[2 * jp + 1][0] = rr[2]; bfr[2 * jp + 1][1] = rr[3];
            }
            #pragma unroll
            for (int i = 0; i < 4; i++)
                #pragma unroll
                for (int j = 0; j < 4; j++)
                    hmma(acc[i][j], afr[i], bfr[j]);
        }
    }

    #pragma unroll
    for (int i = 0; i < 4; i++) {
        int row0 = bm * 128 + wm + i * 16 + g;
        int row1 = row0 + 8;
        float bv0 = bias[row0], bv1 = bias[row1];
        #pragma unroll
        for (int j = 0; j < 4; j++) {
            int col = bn * 128 + wn + j * 8 + 2 * t4;
            if (mode == 0) {
                // fold softmax scale into Q rows (rows < CCH), exact in f32
                float sc0 = (row0 < CCH) ? SCQ : 1.f;
                float sc1 = (row1 < CCH) ? SCQ : 1.f;
                ((uint32_t*)(g_q + (size_t)row0 * NCOLS))[col >> 1] =
                    packf2((acc[i][j][0] + bv0) * sc0, (acc[i][j][1] + bv0) * sc0);
                ((uint32_t*)(g_q + (size_t)row1 * NCOLS))[col >> 1] =
                    packf2((acc[i][j][2] + bv1) * sc1, (acc[i][j][3] + bv1) * sc1);
            } else {
                int bb = col >> 10, n = col & 1023;
                size_t i0 = (size_t)bb * CCH * NSEQ + (size_t)row0 * NSEQ + n;
                size_t i1 = (size_t)bb * CCH * NSEQ + (size_t)row1 * NSEQ + n;
                float2 r0 = *(const float2*)(resid + i0);
                float2 r1 = *(const float2*)(resid + i1);
                float2 o0, o1;
                o0.x = acc[i][j][0] + bv0 + r0.x; o0.y = acc[i][j][1] + bv0 + r0.y;
                o1.x = acc[i][j][2] + bv1 + r1.x; o1.y = acc[i][j][3] + bv1 + r1.y;
                *(float2*)(outP + i0) = o0;
                *(float2*)(outP + i1) = o1;
            }
        }
    }
}

// ---------------------------------------------------------------------------
// Flash attention, fp16 mma, software-pipelined PV:
// PV(t-1) executes at the top of iter t, BEFORE staging tile t+1 overwrites
// its V buffer — overlaps PV tensor work with cp.async and decouples it
// from softmax(t)'s serial scalar chain. Scores already scaled (Q pre-scaled).
// ---------------------------------------------------------------------------
__global__ void __launch_bounds__(256) attn_kernel() {
    const int b = blockIdx.z, h = blockIdx.y, qt = blockIdx.x;
    const int tid = threadIdx.x;
    const int w = tid >> 5, lane = tid & 31;
    const int g = lane >> 2, t4 = lane & 3;
    const int r = lane & 7, jm = lane >> 3;

    __shared__ __align__(16) uint32_t sm[2][2 * 64 * 36];

    const __half* Qb = g_q + (size_t)(h * HD)           * NCOLS + b * NSEQ;
    const __half* Kb = g_q + (size_t)(CCH + h * HD)     * NCOLS + b * NSEQ;
    const __half* Vb = g_q + (size_t)(2 * CCH + h * HD) * NCOLS + b * NSEQ;
    const int qbase = qt * 128;

    const uint32_t s0 = (uint32_t)__cvta_generic_to_shared(&sm[0][0]);
    const uint32_t s1 = (uint32_t)__cvta_generic_to_shared(&sm[1][0]);

    // stage Q [d][qp] stride 68 into sm[0], extract frags (Q pre-scaled)
    {
        uint32_t* q32 = &sm[0][0];
        #pragma unroll
        for (int p = 0; p < 16; p++) {
            int idx = p * 256 + tid;
            int d = idx >> 6, qp = idx & 63;
            q32[d * 68 + qp] = ((const uint32_t*)(Qb + (size_t)d * NCOLS + qbase))[qp];
        }
    }
    __syncthreads();
    uint32_t qa[4][4];
    #pragma unroll
    for (int ks = 0; ks < 4; ks++) {
        uint32_t off = (16 * ks + 8 * (jm >> 1) + r) * 68 + w * 8 + 4 * (jm & 1);
        ldsm4t(qa[ks], s0 + off * 4);
    }
    __syncthreads();

    const int sd = tid >> 3, sch = tid & 7;
    const int sd2 = (256 + tid) >> 3;
    const uint32_t kPart = (8 * (jm & 1) + r) * 36 + 4 * (jm >> 1);
    const uint32_t vPart = ((jm >> 1) * 8 + r) * 36 + 4 * (jm & 1);

    // prologue: stage tile 0 into buf 0
    {
        const char* ksrc = (const char*)(Kb + (size_t)sd * NCOLS);
        const char* ksrc2 = (const char*)(Kb + (size_t)sd2 * NCOLS);
        const char* vsrc = (const char*)(Vb + (size_t)sd * NCOLS);
        const char* vsrc2 = (const char*)(Vb + (size_t)sd2 * NCOLS);
        cpa16(s0 + (sd * 36 + sch * 4) * 4,         ksrc + sch * 16);
        cpa16(s0 + (sd2 * 36 + sch * 4) * 4,        ksrc2 + sch * 16);
        cpa16(s0 + (2304 + sd * 36 + sch * 4) * 4,  vsrc + sch * 16);
        cpa16(s0 + (2304 + sd2 * 36 + sch * 4) * 4, vsrc2 + sch * 16);
        cp_commit();
    }

    float Ov[8][4];
    #pragma unroll
    for (int dc = 0; dc < 8; dc++)
        #pragma unroll
        for (int q = 0; q < 4; q++) Ov[dc][q] = 0.f;
    float m0 = -1e30f, m1 = -1e30f, l0 = 0.f, l1 = 0.f;

    float f0p = 1.f, f1p = 1.f;           // deferred rescale factors
    uint32_t pap[4][4];                   // deferred P fragments
    uint32_t vBp = 0;                     // deferred V buffer base

    for (int kt = 0; kt < NSEQ / 64; kt++) {
        // ---- deferred PV(kt-1): overlaps with staging + softmax phases ----
        if (kt > 0) {
            #pragma unroll
            for (int dc = 0; dc < 8; dc++) {
                Ov[dc][0] *= f0p; Ov[dc][1] *= f0p;
                Ov[dc][2] *= f1p; Ov[dc][3] *= f1p;
            }
            #pragma unroll
            for (int dcp = 0; dcp < 4; dcp++) {
                #pragma unroll
                for (int ks = 0; ks < 4; ks++) {
                    uint32_t rr[4];
                    ldsm4(rr, vBp + ((2 * dcp) * 8 * 36 + 8 * ks + vPart) * 4);
                    hmma(Ov[2 * dcp],     pap[ks], rr);
                    hmma(Ov[2 * dcp + 1], pap[ks], rr + 2);
                }
            }
        }
        __syncthreads();   // all warps done reading old buffers
        if (kt < 15) {
            const int mb = (kt + 1) * 64;
            uint32_t sb = ((kt + 1) & 1) ? s1 : s0;
            const char* ksrc = (const char*)(Kb + (size_t)sd * NCOLS + mb);
            const char* ksrc2 = (const char*)(Kb + (size_t)sd2 * NCOLS + mb);
            const char* vsrc = (const char*)(Vb + (size_t)sd * NCOLS + mb);
            const char* vsrc2 = (const char*)(Vb + (size_t)sd2 * NCOLS + mb);
            cpa16(sb + (sd * 36 + sch * 4) * 4,         ksrc + sch * 16);
            cpa16(sb + (sd2 * 36 + sch * 4) * 4,        ksrc2 + sch * 16);
            cpa16(sb + (2304 + sd * 36 + sch * 4) * 4,  vsrc + sch * 16);
            cpa16(sb + (2304 + sd2 * 36 + sch * 4) * 4, vsrc2 + sch * 16);
            cp_commit();
            cp_wait1();
        } else {
            cp_wait0();
        }
        __syncthreads();

        const uint32_t kB = (kt & 1) ? s1 : s0;
        const uint32_t vB = kB + 2304 * 4;

        // S = Q K^T (already in log2 domain via pre-scaled Q)
        float Csc[8][4];
        #pragma unroll
        for (int mc = 0; mc < 8; mc++)
            #pragma unroll
            for (int q = 0; q < 4; q++) Csc[mc][q] = 0.f;
        #pragma unroll
        for (int p = 0; p < 4; p++) {
            #pragma unroll
            for (int ks = 0; ks < 4; ks++) {
                uint32_t rr[4];
                ldsm4t(rr, kB + (16 * ks * 36 + 8 * p + kPart) * 4);
                hmma(Csc[2 * p],     qa[ks], rr);
                hmma(Csc[2 * p + 1], qa[ks], rr + 2);
            }
        }

        // online softmax (base-2)
        float mx0 = m0, mx1 = m1;
        #pragma unroll
        for (int j = 0; j < 8; j++) {
            mx0 = fmaxf(mx0, fmaxf(Csc[j][0], Csc[j][1]));
            mx1 = fmaxf(mx1, fmaxf(Csc[j][2], Csc[j][3]));
        }
        mx0 = fmaxf(mx0, __shfl_xor_sync(0xffffffffu, mx0, 1));
        mx0 = fmaxf(mx0, __shfl_xor_sync(0xffffffffu, mx0, 2));
        mx1 = fmaxf(mx1, __shfl_xor_sync(0xffffffffu, mx1, 1));
        mx1 = fmaxf(mx1, __shfl_xor_sync(0xffffffffu, mx1, 2));
        float f0 = ex2(m0 - mx0), f1 = ex2(m1 - mx1);
        m0 = mx0; m1 = mx1;

        float ss0 = 0.f, ss1 = 0.f;
        #pragma unroll
        for (int j = 0; j < 8; j++) {
            Csc[j][0] = ex2(Csc[j][0] - mx0);
            Csc[j][1] = ex2(Csc[j][1] - mx0);
            Csc[j][2] = ex2(Csc[j][2] - mx1);
            Csc[j][3] = ex2(Csc[j][3] - mx1);
            ss0 += Csc[j][0] + Csc[j][1];
            ss1 += Csc[j][2] + Csc[j][3];
        }
        ss0 += __shfl_xor_sync(0xffffffffu, ss0, 1);
        ss0 += __shfl_xor_sync(0xffffffffu, ss0, 2);
        ss1 += __shfl_xor_sync(0xffffffffu, ss1, 1);
        ss1 += __shfl_xor_sync(0xffffffffu, ss1, 2);
        l0 = l0 * f0 + ss0;
        l1 = l1 * f1 + ss1;

        // defer P·V: save fragments + factors + buffer for next iteration
        #pragma unroll
        for (int ks = 0; ks < 4; ks++) {
            pap[ks][0] = packf2(Csc[2 * ks][0],     Csc[2 * ks][1]);
            pap[ks][1] = packf2(Csc[2 * ks][2],     Csc[2 * ks][3]);
            pap[ks][2] = packf2(Csc[2 * ks + 1][0], Csc[2 * ks + 1][1]);
            pap[ks][3] = packf2(Csc[2 * ks + 1][2], Csc[2 * ks + 1][3]);
        }
        f0p = f0; f1p = f1;
        vBp = vB;
    }

    // final deferred PV(15)
    {
        #pragma unroll
        for (int dc = 0; dc < 8; dc++) {
            Ov[dc][0] *= f0p; Ov[dc][1] *= f0p;
            Ov[dc][2] *= f1p; Ov[dc][3] *= f1p;
        }
        #pragma unroll
        for (int dcp = 0; dcp < 4; dcp++) {
            #pragma unroll
            for (int ks = 0; ks < 4; ks++) {
                uint32_t rr[4];
                ldsm4(rr, vBp + ((2 * dcp) * 8 * 36 + 8 * ks + vPart) * 4);
                hmma(Ov[2 * dcp],     pap[ks], rr);
                hmma(Ov[2 * dcp + 1], pap[ks], rr + 2);
            }
        }
    }

    // write O (half) to g_oh [C][B*N]
    float inv0 = 1.f / l0, inv1 = 1.f / l1;
    const int q0 = qbase + w * 16 + g;
    #pragma unroll
    for (int dc = 0; dc < 8; dc++) {
        #pragma unroll
        for (int p = 0; p < 2; p++) {
            int d = dc * 8 + 2 * t4 + p;
            __half* base = g_oh + (size_t)(h * HD + d) * NCOLS + b * NSEQ;
            base[q0]     = __float2half_rn(Ov[dc][p] * inv0);
            base[q0 + 8] = __float2half_rn(Ov[dc][2 + p] * inv1);
        }
    }
}

// ---------------------------------------------------------------------------
extern "C" void kernel_launch(void* const* d_in, const int* in_sizes, int n_in,
                              void* d_out, int out_size) {
    const float* x      = (const float*)d_in[0];
    const float* gn_w   = (const float*)d_in[1];
    const float* gn_b   = (const float*)d_in[2];
    const float* qkv_w  = (const float*)d_in[3];
    const float* qkv_b  = (const float*)d_in[4];
    const float* proj_w = (const float*)d_in[5];
    const float* proj_b = (const float*)d_in[6];
    float* out = (float*)d_out;

    gn_kernel<<<BATCH * NGRP, 256>>>(x, gn_w, gn_b);
    prep_w_kernel<<<256, 256>>>(qkv_w, proj_w);

    gemm_kernel<<<dim3(NCOLS / 128, (3 * CCH) / 128), 256>>>(
        qkv_b, nullptr, nullptr, 0);

    attn_kernel<<<dim3(NSEQ / 128, NH, BATCH), 256>>>();

    gemm_kernel<<<dim3(NCOLS / 128, CCH / 128), 256>>>(
        proj_b, out, x, 1);
}

// round 9
// speedup vs baseline: 6.2900x; 1.0469x over previous
#include <cuda_runtime.h>
#include <cuda_fp16.h>
#include <math.h>
#include <stdint.h>

#define BATCH 8
#define CCH   512
#define NSEQ  1024
#define NCOLS 8192
#define NH    8
#define HD    64
#define NGRP  32
#define QW_ELEMS (3 * CCH * CCH)
#define PW_ELEMS (CCH * CCH)
#define SCQ 0.18033688f   // 0.125 * log2(e)

__device__ __half g_xh[CCH * NCOLS];       // xn (half), [C][B*N]
__device__ __half g_wh[QW_ELEMS];          // qkv_w half
__device__ __half g_ph[PW_ELEMS];          // proj_w half
__device__ __half g_q [3 * CCH * NCOLS];   // qkv, [3C][B*N]; Q rows pre-scaled
__device__ __half g_oh[CCH * NCOLS];       // attention out, [C][B*N]

// ---------------- helpers ----------------
__device__ __forceinline__ uint32_t packf2(float lo, float hi) {
    __half2 p = __floats2half2_rn(lo, hi);
    return *reinterpret_cast<uint32_t*>(&p);
}
__device__ __forceinline__ void hmma(float c[4], const uint32_t a[4], const uint32_t b[2]) {
    asm volatile(
        "mma.sync.aligned.m16n8k16.row.col.f32.f16.f16.f32 "
        "{%0,%1,%2,%3}, {%4,%5,%6,%7}, {%8,%9}, {%0,%1,%2,%3};"
        : "+f"(c[0]), "+f"(c[1]), "+f"(c[2]), "+f"(c[3])
        : "r"(a[0]), "r"(a[1]), "r"(a[2]), "r"(a[3]), "r"(b[0]), "r"(b[1]));
}
__device__ __forceinline__ void ldsm4(uint32_t r[4], uint32_t addr) {
    asm volatile("ldmatrix.sync.aligned.m8n8.x4.shared.b16 {%0,%1,%2,%3}, [%4];"
        : "=r"(r[0]), "=r"(r[1]), "=r"(r[2]), "=r"(r[3]) : "r"(addr));
}
__device__ __forceinline__ void ldsm4t(uint32_t r[4], uint32_t addr) {
    asm volatile("ldmatrix.sync.aligned.m8n8.x4.trans.shared.b16 {%0,%1,%2,%3}, [%4];"
        : "=r"(r[0]), "=r"(r[1]), "=r"(r[2]), "=r"(r[3]) : "r"(addr));
}
__device__ __forceinline__ void cpa16(uint32_t dst, const void* src) {
    asm volatile("cp.async.cg.shared.global [%0], [%1], 16;" :: "r"(dst), "l"(src));
}
__device__ __forceinline__ void cp_commit() { asm volatile("cp.async.commit_group;" ::); }
__device__ __forceinline__ void cp_wait0() { asm volatile("cp.async.wait_group 0;" ::); }
__device__ __forceinline__ void cp_wait1() { asm volatile("cp.async.wait_group 1;" ::); }
__device__ __forceinline__ float ex2(float x) {
    float y; asm("ex2.approx.f32 %0, %1;" : "=f"(y) : "f"(x)); return y;
}

// ---------------------------------------------------------------------------
// Fused GroupNorm + weight convert. Blocks [0,256): GN; [256,512): weights.
// ---------------------------------------------------------------------------
__global__ void __launch_bounds__(256) gn_prep_kernel(const float* __restrict__ x,
                                                      const float* __restrict__ gw,
                                                      const float* __restrict__ gb,
                                                      const float* __restrict__ qw,
                                                      const float* __restrict__ pw) {
    if (blockIdx.x >= 256) {
        // ---- weight convert ----
        const int total4 = (QW_ELEMS + PW_ELEMS) / 4;
        for (int i = (blockIdx.x - 256) * 256 + threadIdx.x; i < total4; i += 256 * 256) {
            float4 v;
            uint32_t* dst;
            if (i < QW_ELEMS / 4) {
                v = ((const float4*)qw)[i];
                dst = (uint32_t*)(g_wh + 4 * (size_t)i);
            } else {
                int j = i - QW_ELEMS / 4;
                v = ((const float4*)pw)[j];
                dst = (uint32_t*)(g_ph + 4 * (size_t)j);
            }
            dst[0] = packf2(v.x, v.y);
            dst[1] = packf2(v.z, v.w);
        }
        return;
    }
    // ---- GroupNorm ----
    int bg = blockIdx.x;
    int b = bg >> 5, g = bg & 31;
    const float* xp = x + (size_t)b * CCH * NSEQ + (size_t)g * 16 * NSEQ;

    float s = 0.f, s2 = 0.f;
    for (int i = threadIdx.x; i < 4096; i += 256) {
        float4 v = ((const float4*)xp)[i];
        s  += v.x + v.y + v.z + v.w;
        s2 += v.x*v.x + v.y*v.y + v.z*v.z + v.w*v.w;
    }
    #pragma unroll
    for (int o = 16; o > 0; o >>= 1) {
        s  += __shfl_xor_sync(0xffffffffu, s,  o);
        s2 += __shfl_xor_sync(0xffffffffu, s2, o);
    }
    __shared__ float rs[8], rs2[8];
    if ((threadIdx.x & 31) == 0) { rs[threadIdx.x >> 5] = s; rs2[threadIdx.x >> 5] = s2; }
    __syncthreads();
    float tot = 0.f, tot2 = 0.f;
    #pragma unroll
    for (int i = 0; i < 8; i++) { tot += rs[i]; tot2 += rs2[i]; }
    float mean = tot * (1.f / 16384.f);
    float var  = tot2 * (1.f / 16384.f) - mean * mean;
    float rstd = rsqrtf(var + 1e-5f);

    for (int i = threadIdx.x; i < 4096; i += 256) {
        int c = g * 16 + (i >> 8);
        float4 v = ((const float4*)xp)[i];
        float wch = gw[c] * rstd;
        float bch = gb[c] - mean * wch;
        uint32_t* oh = (uint32_t*)(g_xh + (size_t)c * NCOLS + (size_t)b * NSEQ);
        int j = (i & 255) * 2;
        oh[j]     = packf2(v.x * wch + bch, v.y * wch + bch);
        oh[j + 1] = packf2(v.z * wch + bch, v.w * wch + bch);
    }
}

// ---------------------------------------------------------------------------
// fp16 GEMM: C[M x 8192] = A[M x 512] * B[512 x 8192]  (+bias, +resid)
// mode 0: A=g_wh, B=g_xh, C=g_q (half; Q rows pre-scaled by SCQ).
// mode 1: A=g_ph, B=g_oh, C=out+resid.
// ---------------------------------------------------------------------------
__global__ void __launch_bounds__(256, 2) gemm_kernel(const float* __restrict__ bias,
                                                      float* __restrict__ outP,
                                                      const float* __restrict__ resid,
                                                      int mode) {
    const __half* Ag = mode ? g_ph : g_wh;
    const __half* Bg = mode ? g_oh : g_xh;

    __shared__ __align__(16) uint32_t As[2][128 * 20];
    __shared__ __align__(16) uint32_t Bs[2][32 * 68];

    const int bm = blockIdx.y, bn = blockIdx.x;
    const int tid = threadIdx.x;
    const int w = tid >> 5, lane = tid & 31;
    const int g = lane >> 2, t4 = lane & 3;
    const int r = lane & 7, jm = lane >> 3;
    const int wm = (w >> 2) * 64;
    const int wn = (w & 3) * 32;

    const uint32_t sA0 = (uint32_t)__cvta_generic_to_shared(&As[0][0]);
    const uint32_t sA1 = (uint32_t)__cvta_generic_to_shared(&As[1][0]);
    const uint32_t sB0 = (uint32_t)__cvta_generic_to_shared(&Bs[0][0]);
    const uint32_t sB1 = (uint32_t)__cvta_generic_to_shared(&Bs[1][0]);

    const int am = tid >> 1, ac = tid & 1;
    const char* aSrc = (const char*)(Ag + (size_t)(bm * 128 + am) * CCH);
    const uint32_t aDst = am * 20 + ac * 4;
    const int bk = tid >> 3, bc = tid & 7;
    const uint32_t bDst = bk * 68 + bc * 4;

    const uint32_t aPart = (8 * (jm & 1) + r) * 20 + 4 * (jm >> 1);
    const uint32_t bPart = (8 * (jm & 1) + r) * 68 + (wn >> 1) + 4 * (jm >> 1);

    float acc[4][4][4];
    #pragma unroll
    for (int i = 0; i < 4; i++)
        #pragma unroll
        for (int j = 0; j < 4; j++)
            #pragma unroll
            for (int q = 0; q < 4; q++) acc[i][j][q] = 0.f;

    {
        cpa16(sA0 + (aDst) * 4,       aSrc + ac * 16);
        cpa16(sA0 + (aDst + 8) * 4,   aSrc + ac * 16 + 32);
        const char* bSrc = (const char*)(Bg + (size_t)bk * NCOLS + bn * 128);
        cpa16(sB0 + (bDst) * 4,       bSrc + bc * 16);
        cpa16(sB0 + (bDst + 32) * 4,  bSrc + bc * 16 + 128);
        cp_commit();
    }

    for (int c = 0; c < 16; c++) {
        __syncthreads();
        if (c < 15) {
            int k0 = (c + 1) * 32;
            uint32_t ab = (c + 1) & 1 ? sA1 : sA0;
            uint32_t bb_ = (c + 1) & 1 ? sB1 : sB0;
            cpa16(ab + (aDst) * 4,        aSrc + k0 * 2 + ac * 16);
            cpa16(ab + (aDst + 8) * 4,    aSrc + k0 * 2 + ac * 16 + 32);
            const char* bSrc = (const char*)(Bg + (size_t)(k0 + bk) * NCOLS + bn * 128);
            cpa16(bb_ + (bDst) * 4,       bSrc + bc * 16);
            cpa16(bb_ + (bDst + 32) * 4,  bSrc + bc * 16 + 128);
            cp_commit();
            cp_wait1();
        } else {
            cp_wait0();
        }
        __syncthreads();

        const uint32_t aB = (c & 1) ? sA1 : sA0;
        const uint32_t bB = (c & 1) ? sB1 : sB0;
        #pragma unroll
        for (int ks = 0; ks < 2; ks++) {
            uint32_t afr[4][4], bfr[4][2];
            #pragma unroll
            for (int i = 0; i < 4; i++)
                ldsm4(afr[i], aB + ((wm + i * 16) * 20 + ks * 8 + aPart) * 4);
            #pragma unroll
            for (int jp = 0; jp < 2; jp++) {
                uint32_t rr[4];
                ldsm4t(rr, bB + (16 * ks * 68 + 8 * jp + bPart) * 4);
                bfr[2 * jp][0] = rr[0]; bfr[2 * jp][1] = rr[1];
                bfr[2 * jp + 1][0] = rr[2]; bfr[2 * jp + 1][1] = rr[3];
            }
            #pragma unroll
            for (int i = 0; i < 4; i++)
                #pragma unroll
                for (int j = 0; j < 4; j++)
                    hmma(acc[i][j], afr[i], bfr[j]);
        }
    }

    #pragma unroll
    for (int i = 0; i < 4; i++) {
        int row0 = bm * 128 + wm + i * 16 + g;
        int row1 = row0 + 8;
        float bv0 = bias[row0], bv1 = bias[row1];
        #pragma unroll
        for (int j = 0; j < 4; j++) {
            int col = bn * 128 + wn + j * 8 + 2 * t4;
            if (mode == 0) {
                float sc0 = (row0 < CCH) ? SCQ : 1.f;
                float sc1 = (row1 < CCH) ? SCQ : 1.f;
                ((uint32_t*)(g_q + (size_t)row0 * NCOLS))[col >> 1] =
                    packf2((acc[i][j][0] + bv0) * sc0, (acc[i][j][1] + bv0) * sc0);
                ((uint32_t*)(g_q + (size_t)row1 * NCOLS))[col >> 1] =
                    packf2((acc[i][j][2] + bv1) * sc1, (acc[i][j][3] + bv1) * sc1);
            } else {
                int bb = col >> 10, n = col & 1023;
                size_t i0 = (size_t)bb * CCH * NSEQ + (size_t)row0 * NSEQ + n;
                size_t i1 = (size_t)bb * CCH * NSEQ + (size_t)row1 * NSEQ + n;
                float2 r0 = *(const float2*)(resid + i0);
                float2 r1 = *(const float2*)(resid + i1);
                float2 o0, o1;
                o0.x = acc[i][j][0] + bv0 + r0.x; o0.y = acc[i][j][1] + bv0 + r0.y;
                o1.x = acc[i][j][2] + bv1 + r1.x; o1.y = acc[i][j][3] + bv1 + r1.y;
                *(float2*)(outP + i0) = o0;
                *(float2*)(outP + i1) = o1;
            }
        }
    }
}

// ---------------------------------------------------------------------------
// Flash attention, fp16 mma, deferred PV. Row-sum l computed ON TENSOR CORES:
// a constant ones-column B fragment (lanes n=0 hold half2(1,1)) accumulates
// l = P·1 alongside the PV MMAs — removes the 16 FADD + 4 serial SHFL
// row-sum chain from every softmax round. Only the max reduction remains.
// ---------------------------------------------------------------------------
__global__ void __launch_bounds__(256) attn_kernel() {
    const int b = blockIdx.z, h = blockIdx.y, qt = blockIdx.x;
    const int tid = threadIdx.x;
    const int w = tid >> 5, lane = tid & 31;
    const int g = lane >> 2, t4 = lane & 3;
    const int r = lane & 7, jm = lane >> 3;

    __shared__ __align__(16) uint32_t sm[2][2 * 64 * 36];

    const __half* Qb = g_q + (size_t)(h * HD)           * NCOLS + b * NSEQ;
    const __half* Kb = g_q + (size_t)(CCH + h * HD)     * NCOLS + b * NSEQ;
    const __half* Vb = g_q + (size_t)(2 * CCH + h * HD) * NCOLS + b * NSEQ;
    const int qbase = qt * 128;

    const uint32_t s0 = (uint32_t)__cvta_generic_to_shared(&sm[0][0]);
    const uint32_t s1 = (uint32_t)__cvta_generic_to_shared(&sm[1][0]);

    // stage Q [d][qp] stride 68 into sm[0], extract frags (Q pre-scaled)
    {
        uint32_t* q32 = &sm[0][0];
        #pragma unroll
        for (int p = 0; p < 16; p++) {
            int idx = p * 256 + tid;
            int d = idx >> 6, qp = idx & 63;
            q32[d * 68 + qp] = ((const uint32_t*)(Qb + (size_t)d * NCOLS + qbase))[qp];
        }
    }
    __syncthreads();
    uint32_t qa[4][4];
    #pragma unroll
    for (int ks = 0; ks < 4; ks++) {
        uint32_t off = (16 * ks + 8 * (jm >> 1) + r) * 68 + w * 8 + 4 * (jm & 1);
        ldsm4t(qa[ks], s0 + off * 4);
    }
    __syncthreads();

    const int sd = tid >> 3, sch = tid & 7;
    const int sd2 = (256 + tid) >> 3;
    const uint32_t kPart = (8 * (jm & 1) + r) * 36 + 4 * (jm >> 1);
    const uint32_t vPart = ((jm >> 1) * 8 + r) * 36 + 4 * (jm & 1);

    // ones B-frag for l = P·1: column n=0 (lanes 0-3) holds half2(1,1)
    uint32_t onesB[2];
    onesB[0] = (lane < 4) ? 0x3C003C00u : 0u;
    onesB[1] = onesB[0];

    // prologue: stage tile 0 into buf 0
    {
        const char* ksrc = (const char*)(Kb + (size_t)sd * NCOLS);
        const char* ksrc2 = (const char*)(Kb + (size_t)sd2 * NCOLS);
        const char* vsrc = (const char*)(Vb + (size_t)sd * NCOLS);
        const char* vsrc2 = (const char*)(Vb + (size_t)sd2 * NCOLS);
        cpa16(s0 + (sd * 36 + sch * 4) * 4,         ksrc + sch * 16);
        cpa16(s0 + (sd2 * 36 + sch * 4) * 4,        ksrc2 + sch * 16);
        cpa16(s0 + (2304 + sd * 36 + sch * 4) * 4,  vsrc + sch * 16);
        cpa16(s0 + (2304 + sd2 * 36 + sch * 4) * 4, vsrc2 + sch * 16);
        cp_commit();
    }

    float Ov[8][4];
    #pragma unroll
    for (int dc = 0; dc < 8; dc++)
        #pragma unroll
        for (int q = 0; q < 4; q++) Ov[dc][q] = 0.f;
    float lC[4] = {0.f, 0.f, 0.f, 0.f};   // l accumulator (C-frag, col 0)
    float m0 = -1e30f, m1 = -1e30f;

    float f0p = 1.f, f1p = 1.f;
    uint32_t pap[4][4];
    uint32_t vBp = 0;

    for (int kt = 0; kt < NSEQ / 64; kt++) {
        // ---- deferred PV(kt-1) + l accumulation ----
        if (kt > 0) {
            #pragma unroll
            for (int dc = 0; dc < 8; dc++) {
                Ov[dc][0] *= f0p; Ov[dc][1] *= f0p;
                Ov[dc][2] *= f1p; Ov[dc][3] *= f1p;
            }
            lC[0] *= f0p; lC[1] *= f0p; lC[2] *= f1p; lC[3] *= f1p;
            #pragma unroll
            for (int ks = 0; ks < 4; ks++)
                hmma(lC, pap[ks], onesB);
            #pragma unroll
            for (int dcp = 0; dcp < 4; dcp++) {
                #pragma unroll
                for (int ks = 0; ks < 4; ks++) {
                    uint32_t rr[4];
                    ldsm4(rr, vBp + ((2 * dcp) * 8 * 36 + 8 * ks + vPart) * 4);
                    hmma(Ov[2 * dcp],     pap[ks], rr);
                    hmma(Ov[2 * dcp + 1], pap[ks], rr + 2);
                }
            }
        }
        __syncthreads();
        if (kt < 15) {
            const int mb = (kt + 1) * 64;
            uint32_t sb = ((kt + 1) & 1) ? s1 : s0;
            const char* ksrc = (const char*)(Kb + (size_t)sd * NCOLS + mb);
            const char* ksrc2 = (const char*)(Kb + (size_t)sd2 * NCOLS + mb);
            const char* vsrc = (const char*)(Vb + (size_t)sd * NCOLS + mb);
            const char* vsrc2 = (const char*)(Vb + (size_t)sd2 * NCOLS + mb);
            cpa16(sb + (sd * 36 + sch * 4) * 4,         ksrc + sch * 16);
            cpa16(sb + (sd2 * 36 + sch * 4) * 4,        ksrc2 + sch * 16);
            cpa16(sb + (2304 + sd * 36 + sch * 4) * 4,  vsrc + sch * 16);
            cpa16(sb + (2304 + sd2 * 36 + sch * 4) * 4, vsrc2 + sch * 16);
            cp_commit();
            cp_wait1();
        } else {
            cp_wait0();
        }
        __syncthreads();

        const uint32_t kB = (kt & 1) ? s1 : s0;
        const uint32_t vB = kB + 2304 * 4;

        // S = Q K^T (log2 domain, Q pre-scaled)
        float Csc[8][4];
        #pragma unroll
        for (int mc = 0; mc < 8; mc++)
            #pragma unroll
            for (int q = 0; q < 4; q++) Csc[mc][q] = 0.f;
        #pragma unroll
        for (int p = 0; p < 4; p++) {
            #pragma unroll
            for (int ks = 0; ks < 4; ks++) {
                uint32_t rr[4];
                ldsm4t(rr, kB + (16 * ks * 36 + 8 * p + kPart) * 4);
                hmma(Csc[2 * p],     qa[ks], rr);
                hmma(Csc[2 * p + 1], qa[ks], rr + 2);
            }
        }

        // online softmax (base-2): max reduction only
        float mx0 = m0, mx1 = m1;
        #pragma unroll
        for (int j = 0; j < 8; j++) {
            mx0 = fmaxf(mx0, fmaxf(Csc[j][0], Csc[j][1]));
            mx1 = fmaxf(mx1, fmaxf(Csc[j][2], Csc[j][3]));
        }
        mx0 = fmaxf(mx0, __shfl_xor_sync(0xffffffffu, mx0, 1));
        mx0 = fmaxf(mx0, __shfl_xor_sync(0xffffffffu, mx0, 2));
        mx1 = fmaxf(mx1, __shfl_xor_sync(0xffffffffu, mx1, 1));
        mx1 = fmaxf(mx1, __shfl_xor_sync(0xffffffffu, mx1, 2));
        float f0 = ex2(m0 - mx0), f1 = ex2(m1 - mx1);
        m0 = mx0; m1 = mx1;

        // p = 2^(s - max); pack straight into deferred A-frags
        #pragma unroll
        for (int ks = 0; ks < 4; ks++) {
            pap[ks][0] = packf2(ex2(Csc[2 * ks][0] - mx0),     ex2(Csc[2 * ks][1] - mx0));
            pap[ks][1] = packf2(ex2(Csc[2 * ks][2] - mx1),     ex2(Csc[2 * ks][3] - mx1));
            pap[ks][2] = packf2(ex2(Csc[2 * ks + 1][0] - mx0), ex2(Csc[2 * ks + 1][1] - mx0));
            pap[ks][3] = packf2(ex2(Csc[2 * ks + 1][2] - mx1), ex2(Csc[2 * ks + 1][3] - mx1));
        }
        f0p = f0; f1p = f1;
        vBp = vB;
    }

    // final deferred PV(15) + l
    {
        #pragma unroll
        for (int dc = 0; dc < 8; dc++) {
            Ov[dc][0] *= f0p; Ov[dc][1] *= f0p;
            Ov[dc][2] *= f1p; Ov[dc][3] *= f1p;
        }
        lC[0] *= f0p; lC[1] *= f0p; lC[2] *= f1p; lC[3] *= f1p;
        #pragma unroll
        for (int ks = 0; ks < 4; ks++)
            hmma(lC, pap[ks], onesB);
        #pragma unroll
        for (int dcp = 0; dcp < 4; dcp++) {
            #pragma unroll
            for (int ks = 0; ks < 4; ks++) {
                uint32_t rr[4];
                ldsm4(rr, vBp + ((2 * dcp) * 8 * 36 + 8 * ks + vPart) * 4);
                hmma(Ov[2 * dcp],     pap[ks], rr);
                hmma(Ov[2 * dcp + 1], pap[ks], rr + 2);
            }
        }
    }

    // broadcast l (column 0 lives on lanes t4==0)
    float l0 = __shfl_sync(0xffffffffu, lC[0], lane & ~3);
    float l1 = __shfl_sync(0xffffffffu, lC[2], lane & ~3);

    // write O (half) to g_oh [C][B*N]
    float inv0 = 1.f / l0, inv1 = 1.f / l1;
    const int q0 = qbase + w * 16 + g;
    #pragma unroll
    for (int dc = 0; dc < 8; dc++) {
        #pragma unroll
        for (int p = 0; p < 2; p++) {
            int d = dc * 8 + 2 * t4 + p;
            __half* base = g_oh + (size_t)(h * HD + d) * NCOLS + b * NSEQ;
            base[q0]     = __float2half_rn(Ov[dc][p] * inv0);
            base[q0 + 8] = __float2half_rn(Ov[dc][2 + p] * inv1);
        }
    }
}

// ---------------------------------------------------------------------------
extern "C" void kernel_launch(void* const* d_in, const int* in_sizes, int n_in,
                              void* d_out, int out_size) {
    const float* x      = (const float*)d_in[0];
    const float* gn_w   = (const float*)d_in[1];
    const float* gn_b   = (const float*)d_in[2];
    const float* qkv_w  = (const float*)d_in[3];
    const float* qkv_b  = (const float*)d_in[4];
    const float* proj_w = (const float*)d_in[5];
    const float* proj_b = (const float*)d_in[6];
    float* out = (float*)d_out;

    gn_prep_kernel<<<512, 256>>>(x, gn_w, gn_b, qkv_w, proj_w);

    gemm_kernel<<<dim3(NCOLS / 128, (3 * CCH) / 128), 256>>>(
        qkv_b, nullptr, nullptr, 0);

    attn_kernel<<<dim3(NSEQ / 128, NH, BATCH), 256>>>();

    gemm_kernel<<<dim3(NCOLS / 128, CCH / 128), 256>>>(
        proj_b, out, x, 1);
}

// round 10
// speedup vs baseline: 6.5759x; 1.0455x over previous
#include <cuda_runtime.h>
#include <cuda_fp16.h>
#include <math.h>
#include <stdint.h>

#define BATCH 8
#define CCH   512
#define NSEQ  1024
#define NCOLS 8192
#define NH    8
#define HD    64
#define NGRP  32
#define QW_ELEMS (3 * CCH * CCH)
#define PW_ELEMS (CCH * CCH)
#define SCQ 0.18033688f   // 0.125 * log2(e)

__device__ __half g_xh[CCH * NCOLS];       // xn (half), [C][B*N]
__device__ __half g_wh[QW_ELEMS];          // qkv_w half
__device__ __half g_ph[PW_ELEMS];          // proj_w half
__device__ __half g_q [3 * CCH * NCOLS];   // qkv, [3C][B*N]; Q rows pre-scaled
__device__ __half g_oh[CCH * NCOLS];       // attention out, [C][B*N]

// ---------------- helpers ----------------
__device__ __forceinline__ uint32_t packf2(float lo, float hi) {
    __half2 p = __floats2half2_rn(lo, hi);
    return *reinterpret_cast<uint32_t*>(&p);
}
__device__ __forceinline__ void hmma(float c[4], const uint32_t a[4], const uint32_t b[2]) {
    asm volatile(
        "mma.sync.aligned.m16n8k16.row.col.f32.f16.f16.f32 "
        "{%0,%1,%2,%3}, {%4,%5,%6,%7}, {%8,%9}, {%0,%1,%2,%3};"
        : "+f"(c[0]), "+f"(c[1]), "+f"(c[2]), "+f"(c[3])
        : "r"(a[0]), "r"(a[1]), "r"(a[2]), "r"(a[3]), "r"(b[0]), "r"(b[1]));
}
__device__ __forceinline__ void ldsm4(uint32_t r[4], uint32_t addr) {
    asm volatile("ldmatrix.sync.aligned.m8n8.x4.shared.b16 {%0,%1,%2,%3}, [%4];"
        : "=r"(r[0]), "=r"(r[1]), "=r"(r[2]), "=r"(r[3]) : "r"(addr));
}
__device__ __forceinline__ void ldsm4t(uint32_t r[4], uint32_t addr) {
    asm volatile("ldmatrix.sync.aligned.m8n8.x4.trans.shared.b16 {%0,%1,%2,%3}, [%4];"
        : "=r"(r[0]), "=r"(r[1]), "=r"(r[2]), "=r"(r[3]) : "r"(addr));
}
__device__ __forceinline__ void cpa16(uint32_t dst, const void* src) {
    asm volatile("cp.async.cg.shared.global [%0], [%1], 16;" :: "r"(dst), "l"(src));
}
__device__ __forceinline__ void cp_commit() { asm volatile("cp.async.commit_group;" ::); }
__device__ __forceinline__ void cp_wait0() { asm volatile("cp.async.wait_group 0;" ::); }
__device__ __forceinline__ void cp_wait1() { asm volatile("cp.async.wait_group 1;" ::); }
__device__ __forceinline__ float ex2(float x) {
    float y; asm("ex2.approx.f32 %0, %1;" : "=f"(y) : "f"(x)); return y;
}

// ---------------------------------------------------------------------------
// Fused GroupNorm + weight convert. Blocks [0,256): GN; [256,512): weights.
// ---------------------------------------------------------------------------
__global__ void __launch_bounds__(256) gn_prep_kernel(const float* __restrict__ x,
                                                      const float* __restrict__ gw,
                                                      const float* __restrict__ gb,
                                                      const float* __restrict__ qw,
                                                      const float* __restrict__ pw) {
    if (blockIdx.x >= 256) {
        const int total4 = (QW_ELEMS + PW_ELEMS) / 4;
        for (int i = (blockIdx.x - 256) * 256 + threadIdx.x; i < total4; i += 256 * 256) {
            float4 v;
            uint32_t* dst;
            if (i < QW_ELEMS / 4) {
                v = ((const float4*)qw)[i];
                dst = (uint32_t*)(g_wh + 4 * (size_t)i);
            } else {
                int j = i - QW_ELEMS / 4;
                v = ((const float4*)pw)[j];
                dst = (uint32_t*)(g_ph + 4 * (size_t)j);
            }
            dst[0] = packf2(v.x, v.y);
            dst[1] = packf2(v.z, v.w);
        }
        return;
    }
    int bg = blockIdx.x;
    int b = bg >> 5, g = bg & 31;
    const float* xp = x + (size_t)b * CCH * NSEQ + (size_t)g * 16 * NSEQ;

    float s = 0.f, s2 = 0.f;
    for (int i = threadIdx.x; i < 4096; i += 256) {
        float4 v = ((const float4*)xp)[i];
        s  += v.x + v.y + v.z + v.w;
        s2 += v.x*v.x + v.y*v.y + v.z*v.z + v.w*v.w;
    }
    #pragma unroll
    for (int o = 16; o > 0; o >>= 1) {
        s  += __shfl_xor_sync(0xffffffffu, s,  o);
        s2 += __shfl_xor_sync(0xffffffffu, s2, o);
    }
    __shared__ float rs[8], rs2[8];
    if ((threadIdx.x & 31) == 0) { rs[threadIdx.x >> 5] = s; rs2[threadIdx.x >> 5] = s2; }
    __syncthreads();
    float tot = 0.f, tot2 = 0.f;
    #pragma unroll
    for (int i = 0; i < 8; i++) { tot += rs[i]; tot2 += rs2[i]; }
    float mean = tot * (1.f / 16384.f);
    float var  = tot2 * (1.f / 16384.f) - mean * mean;
    float rstd = rsqrtf(var + 1e-5f);

    for (int i = threadIdx.x; i < 4096; i += 256) {
        int c = g * 16 + (i >> 8);
        float4 v = ((const float4*)xp)[i];
        float wch = gw[c] * rstd;
        float bch = gb[c] - mean * wch;
        uint32_t* oh = (uint32_t*)(g_xh + (size_t)c * NCOLS + (size_t)b * NSEQ);
        int j = (i & 255) * 2;
        oh[j]     = packf2(v.x * wch + bch, v.y * wch + bch);
        oh[j + 1] = packf2(v.z * wch + bch, v.w * wch + bch);
    }
}

// ---------------------------------------------------------------------------
// fp16 GEMM: C[M x 8192] = A[M x 512] * B[512 x 8192]  (+bias, +resid)
// mode 0: A=g_wh, B=g_xh, C=g_q (half; Q rows pre-scaled by SCQ).
// mode 1: A=g_ph, B=g_oh, C=out+resid.
// ---------------------------------------------------------------------------
__global__ void __launch_bounds__(256, 2) gemm_kernel(const float* __restrict__ bias,
                                                      float* __restrict__ outP,
                                                      const float* __restrict__ resid,
                                                      int mode) {
    const __half* Ag = mode ? g_ph : g_wh;
    const __half* Bg = mode ? g_oh : g_xh;

    __shared__ __align__(16) uint32_t As[2][128 * 20];
    __shared__ __align__(16) uint32_t Bs[2][32 * 68];

    const int bm = blockIdx.y, bn = blockIdx.x;
    const int tid = threadIdx.x;
    const int w = tid >> 5, lane = tid & 31;
    const int g = lane >> 2, t4 = lane & 3;
    const int r = lane & 7, jm = lane >> 3;
    const int wm = (w >> 2) * 64;
    const int wn = (w & 3) * 32;

    const uint32_t sA0 = (uint32_t)__cvta_generic_to_shared(&As[0][0]);
    const uint32_t sA1 = (uint32_t)__cvta_generic_to_shared(&As[1][0]);
    const uint32_t sB0 = (uint32_t)__cvta_generic_to_shared(&Bs[0][0]);
    const uint32_t sB1 = (uint32_t)__cvta_generic_to_shared(&Bs[1][0]);

    const int am = tid >> 1, ac = tid & 1;
    const char* aSrc = (const char*)(Ag + (size_t)(bm * 128 + am) * CCH);
    const uint32_t aDst = am * 20 + ac * 4;
    const int bk = tid >> 3, bc = tid & 7;
    const uint32_t bDst = bk * 68 + bc * 4;

    const uint32_t aPart = (8 * (jm & 1) + r) * 20 + 4 * (jm >> 1);
    const uint32_t bPart = (8 * (jm & 1) + r) * 68 + (wn >> 1) + 4 * (jm >> 1);

    float acc[4][4][4];
    #pragma unroll
    for (int i = 0; i < 4; i++)
        #pragma unroll
        for (int j = 0; j < 4; j++)
            #pragma unroll
            for (int q = 0; q < 4; q++) acc[i][j][q] = 0.f;

    {
        cpa16(sA0 + (aDst) * 4,       aSrc + ac * 16);
        cpa16(sA0 + (aDst + 8) * 4,   aSrc + ac * 16 + 32);
        const char* bSrc = (const char*)(Bg + (size_t)bk * NCOLS + bn * 128);
        cpa16(sB0 + (bDst) * 4,       bSrc + bc * 16);
        cpa16(sB0 + (bDst + 32) * 4,  bSrc + bc * 16 + 128);
        cp_commit();
    }

    for (int c = 0; c < 16; c++) {
        __syncthreads();
        if (c < 15) {
            int k0 = (c + 1) * 32;
            uint32_t ab = (c + 1) & 1 ? sA1 : sA0;
            uint32_t bb_ = (c + 1) & 1 ? sB1 : sB0;
            cpa16(ab + (aDst) * 4,        aSrc + k0 * 2 + ac * 16);
            cpa16(ab + (aDst + 8) * 4,    aSrc + k0 * 2 + ac * 16 + 32);
            const char* bSrc = (const char*)(Bg + (size_t)(k0 + bk) * NCOLS + bn * 128);
            cpa16(bb_ + (bDst) * 4,       bSrc + bc * 16);
            cpa16(bb_ + (bDst + 32) * 4,  bSrc + bc * 16 + 128);
            cp_commit();
            cp_wait1();
        } else {
            cp_wait0();
        }
        __syncthreads();

        const uint32_t aB = (c & 1) ? sA1 : sA0;
        const uint32_t bB = (c & 1) ? sB1 : sB0;
        #pragma unroll
        for (int ks = 0; ks < 2; ks++) {
            uint32_t afr[4][4], bfr[4][2];
            #pragma unroll
            for (int i = 0; i < 4; i++)
                ldsm4(afr[i], aB + ((wm + i * 16) * 20 + ks * 8 + aPart) * 4);
            #pragma unroll
            for (int jp = 0; jp < 2; jp++) {
                uint32_t rr[4];
                ldsm4t(rr, bB + (16 * ks * 68 + 8 * jp + bPart) * 4);
                bfr[2 * jp][0] = rr[0]; bfr[2 * jp][1] = rr[1];
                bfr[2 * jp + 1][0] = rr[2]; bfr[2 * jp + 1][1] = rr[3];
            }
            #pragma unroll
            for (int i = 0; i < 4; i++)
                #pragma unroll
                for (int j = 0; j < 4; j++)
                    hmma(acc[i][j], afr[i], bfr[j]);
        }
    }

    #pragma unroll
    for (int i = 0; i < 4; i++) {
        int row0 = bm * 128 + wm + i * 16 + g;
        int row1 = row0 + 8;
        float bv0 = bias[row0], bv1 = bias[row1];
        #pragma unroll
        for (int j = 0; j < 4; j++) {
            int col = bn * 128 + wn + j * 8 + 2 * t4;
            if (mode == 0) {
                float sc0 = (row0 < CCH) ? SCQ : 1.f;
                float sc1 = (row1 < CCH) ? SCQ : 1.f;
                ((uint32_t*)(g_q + (size_t)row0 * NCOLS))[col >> 1] =
                    packf2((acc[i][j][0] + bv0) * sc0, (acc[i][j][1] + bv0) * sc0);
                ((uint32_t*)(g_q + (size_t)row1 * NCOLS))[col >> 1] =
                    packf2((acc[i][j][2] + bv1) * sc1, (acc[i][j][3] + bv1) * sc1);
            } else {
                int bb = col >> 10, n = col & 1023;
                size_t i0 = (size_t)bb * CCH * NSEQ + (size_t)row0 * NSEQ + n;
                size_t i1 = (size_t)bb * CCH * NSEQ + (size_t)row1 * NSEQ + n;
                float2 r0 = *(const float2*)(resid + i0);
                float2 r1 = *(const float2*)(resid + i1);
                float2 o0, o1;
                o0.x = acc[i][j][0] + bv0 + r0.x; o0.y = acc[i][j][1] + bv0 + r0.y;
                o1.x = acc[i][j][2] + bv1 + r1.x; o1.y = acc[i][j][3] + bv1 + r1.y;
                *(float2*)(outP + i0) = o0;
                *(float2*)(outP + i1) = o1;
            }
        }
    }
}

// ---------------------------------------------------------------------------
// Flash attention, fp16 mma, deferred PV + tensor-core row-sum.
// 128-thread CTAs (4 warps, 64 q rows): same smem/CTA, 5 CTAs/SM resident
// (vs 2 at 256 thr) -> +43% warps for latency hiding, 1.38 waves (vs 1.73).
// ---------------------------------------------------------------------------
__global__ void __launch_bounds__(128) attn_kernel() {
    const int b = blockIdx.z, h = blockIdx.y, qt = blockIdx.x;
    const int tid = threadIdx.x;
    const int w = tid >> 5, lane = tid & 31;
    const int g = lane >> 2, t4 = lane & 3;
    const int r = lane & 7, jm = lane >> 3;

    __shared__ __align__(16) uint32_t sm[2][2 * 64 * 36];

    const __half* Qb = g_q + (size_t)(h * HD)           * NCOLS + b * NSEQ;
    const __half* Kb = g_q + (size_t)(CCH + h * HD)     * NCOLS + b * NSEQ;
    const __half* Vb = g_q + (size_t)(2 * CCH + h * HD) * NCOLS + b * NSEQ;
    const int qbase = qt * 64;

    const uint32_t s0 = (uint32_t)__cvta_generic_to_shared(&sm[0][0]);
    const uint32_t s1 = (uint32_t)__cvta_generic_to_shared(&sm[1][0]);

    // stage Q [d 64][qp 32] stride 36 into sm[0] (2304 u32), extract frags
    {
        uint32_t* q32 = &sm[0][0];
        #pragma unroll
        for (int p = 0; p < 16; p++) {
            int idx = p * 128 + tid;
            int d = idx >> 5, qp = idx & 31;
            q32[d * 36 + qp] = ((const uint32_t*)(Qb + (size_t)d * NCOLS + qbase))[qp];
        }
    }
    __syncthreads();
    uint32_t qa[4][4];
    #pragma unroll
    for (int ks = 0; ks < 4; ks++) {
        uint32_t off = (16 * ks + 8 * (jm >> 1) + r) * 36 + w * 8 + 4 * (jm & 1);
        ldsm4t(qa[ks], s0 + off * 4);
    }
    __syncthreads();

    // staging map: 8 cpa16/thread/tile; ch const per thread
    const int rowbase = tid >> 3, ch = tid & 7;
    const uint32_t kPart = (8 * (jm & 1) + r) * 36 + 4 * (jm >> 1);
    const uint32_t vPart = ((jm >> 1) * 8 + r) * 36 + 4 * (jm & 1);

    // ones B-frag for l = P·1 (col n=0 holds half2(1,1))
    uint32_t onesB[2];
    onesB[0] = (lane < 4) ? 0x3C003C00u : 0u;
    onesB[1] = onesB[0];

    // prologue: stage tile 0 into buf 0
    {
        #pragma unroll
        for (int p = 0; p < 4; p++) {
            int d = p * 16 + rowbase;
            cpa16(s0 + (d * 36 + ch * 4) * 4,
                  (const char*)(Kb + (size_t)d * NCOLS) + ch * 16);
            cpa16(s0 + (2304 + d * 36 + ch * 4) * 4,
                  (const char*)(Vb + (size_t)d * NCOLS) + ch * 16);
        }
        cp_commit();
    }

    float Ov[8][4];
    #pragma unroll
    for (int dc = 0; dc < 8; dc++)
        #pragma unroll
        for (int q = 0; q < 4; q++) Ov[dc][q] = 0.f;
    float lC[4] = {0.f, 0.f, 0.f, 0.f};
    float m0 = -1e30f, m1 = -1e30f;

    float f0p = 1.f, f1p = 1.f;
    uint32_t pap[4][4];
    uint32_t vBp = 0;

    for (int kt = 0; kt < NSEQ / 64; kt++) {
        // ---- deferred PV(kt-1) + l accumulation ----
        if (kt > 0) {
            #pragma unroll
            for (int dc = 0; dc < 8; dc++) {
                Ov[dc][0] *= f0p; Ov[dc][1] *= f0p;
                Ov[dc][2] *= f1p; Ov[dc][3] *= f1p;
            }
            lC[0] *= f0p; lC[1] *= f0p; lC[2] *= f1p; lC[3] *= f1p;
            #pragma unroll
            for (int ks = 0; ks < 4; ks++)
                hmma(lC, pap[ks], onesB);
            #pragma unroll
            for (int dcp = 0; dcp < 4; dcp++) {
                #pragma unroll
                for (int ks = 0; ks < 4; ks++) {
                    uint32_t rr[4];
                    ldsm4(rr, vBp + ((2 * dcp) * 8 * 36 + 8 * ks + vPart) * 4);
                    hmma(Ov[2 * dcp],     pap[ks], rr);
                    hmma(Ov[2 * dcp + 1], pap[ks], rr + 2);
                }
            }
        }
        __syncthreads();
        if (kt < 15) {
            const int mb = (kt + 1) * 64;
            uint32_t sb = ((kt + 1) & 1) ? s1 : s0;
            #pragma unroll
            for (int p = 0; p < 4; p++) {
                int d = p * 16 + rowbase;
                cpa16(sb + (d * 36 + ch * 4) * 4,
                      (const char*)(Kb + (size_t)d * NCOLS + mb) + ch * 16);
                cpa16(sb + (2304 + d * 36 + ch * 4) * 4,
                      (const char*)(Vb + (size_t)d * NCOLS + mb) + ch * 16);
            }
            cp_commit();
            cp_wait1();
        } else {
            cp_wait0();
        }
        __syncthreads();

        const uint32_t kB = (kt & 1) ? s1 : s0;
        const uint32_t vB = kB + 2304 * 4;

        // S = Q K^T (log2 domain, Q pre-scaled)
        float Csc[8][4];
        #pragma unroll
        for (int mc = 0; mc < 8; mc++)
            #pragma unroll
            for (int q = 0; q < 4; q++) Csc[mc][q] = 0.f;
        #pragma unroll
        for (int p = 0; p < 4; p++) {
            #pragma unroll
            for (int ks = 0; ks < 4; ks++) {
                uint32_t rr[4];
                ldsm4t(rr, kB + (16 * ks * 36 + 8 * p + kPart) * 4);
                hmma(Csc[2 * p],     qa[ks], rr);
                hmma(Csc[2 * p + 1], qa[ks], rr + 2);
            }
        }

        // online softmax (base-2): max reduction only
        float mx0 = m0, mx1 = m1;
        #pragma unroll
        for (int j = 0; j < 8; j++) {
            mx0 = fmaxf(mx0, fmaxf(Csc[j][0], Csc[j][1]));
            mx1 = fmaxf(mx1, fmaxf(Csc[j][2], Csc[j][3]));
        }
        mx0 = fmaxf(mx0, __shfl_xor_sync(0xffffffffu, mx0, 1));
        mx0 = fmaxf(mx0, __shfl_xor_sync(0xffffffffu, mx0, 2));
        mx1 = fmaxf(mx1, __shfl_xor_sync(0xffffffffu, mx1, 1));
        mx1 = fmaxf(mx1, __shfl_xor_sync(0xffffffffu, mx1, 2));
        float f0 = ex2(m0 - mx0), f1 = ex2(m1 - mx1);
        m0 = mx0; m1 = mx1;

        // p = 2^(s - max); pack straight into deferred A-frags
        #pragma unroll
        for (int ks = 0; ks < 4; ks++) {
            pap[ks][0] = packf2(ex2(Csc[2 * ks][0] - mx0),     ex2(Csc[2 * ks][1] - mx0));
            pap[ks][1] = packf2(ex2(Csc[2 * ks][2] - mx1),     ex2(Csc[2 * ks][3] - mx1));
            pap[ks][2] = packf2(ex2(Csc[2 * ks + 1][0] - mx0), ex2(Csc[2 * ks + 1][1] - mx0));
            pap[ks][3] = packf2(ex2(Csc[2 * ks + 1][2] - mx1), ex2(Csc[2 * ks + 1][3] - mx1));
        }
        f0p = f0; f1p = f1;
        vBp = vB;
    }

    // final deferred PV(15) + l
    {
        #pragma unroll
        for (int dc = 0; dc < 8; dc++) {
            Ov[dc][0] *= f0p; Ov[dc][1] *= f0p;
            Ov[dc][2] *= f1p; Ov[dc][3] *= f1p;
        }
        lC[0] *= f0p; lC[1] *= f0p; lC[2] *= f1p; lC[3] *= f1p;
        #pragma unroll
        for (int ks = 0; ks < 4; ks++)
            hmma(lC, pap[ks], onesB);
        #pragma unroll
        for (int dcp = 0; dcp < 4; dcp++) {
            #pragma unroll
            for (int ks = 0; ks < 4; ks++) {
                uint32_t rr[4];
                ldsm4(rr, vBp + ((2 * dcp) * 8 * 36 + 8 * ks + vPart) * 4);
                hmma(Ov[2 * dcp],     pap[ks], rr);
                hmma(Ov[2 * dcp + 1], pap[ks], rr + 2);
            }
        }
    }

    float l0 = __shfl_sync(0xffffffffu, lC[0], lane & ~3);
    float l1 = __shfl_sync(0xffffffffu, lC[2], lane & ~3);

    // write O (half) to g_oh [C][B*N]
    float inv0 = 1.f / l0, inv1 = 1.f / l1;
    const int q0 = qbase + w * 16 + g;
    #pragma unroll
    for (int dc = 0; dc < 8; dc++) {
        #pragma unroll
        for (int p = 0; p < 2; p++) {
            int d = dc * 8 + 2 * t4 + p;
            __half* base = g_oh + (size_t)(h * HD + d) * NCOLS + b * NSEQ;
            base[q0]     = __float2half_rn(Ov[dc][p] * inv0);
            base[q0 + 8] = __float2half_rn(Ov[dc][2 + p] * inv1);
        }
    }
}

// ---------------------------------------------------------------------------
extern "C" void kernel_launch(void* const* d_in, const int* in_sizes, int n_in,
                              void* d_out, int out_size) {
    const float* x      = (const float*)d_in[0];
    const float* gn_w   = (const float*)d_in[1];
    const float* gn_b   = (const float*)d_in[2];
    const float* qkv_w  = (const float*)d_in[3];
    const float* qkv_b  = (const float*)d_in[4];
    const float* proj_w = (const float*)d_in[5];
    const float* proj_b = (const float*)d_in[6];
    float* out = (float*)d_out;

    gn_prep_kernel<<<512, 256>>>(x, gn_w, gn_b, qkv_w, proj_w);

    gemm_kernel<<<dim3(NCOLS / 128, (3 * CCH) / 128), 256>>>(
        qkv_b, nullptr, nullptr, 0);

    attn_kernel<<<dim3(NSEQ / 64, NH, BATCH), 128>>>();

    gemm_kernel<<<dim3(NCOLS / 128, CCH / 128), 256>>>(
        proj_b, out, x, 1);
}